// round 1
// baseline (speedup 1.0000x reference)
#include <cuda_runtime.h>
#include <cuda_bf16.h>
#include <math.h>

// Problem constants
#define BB 4
#define TT 2048
#define CC 1024
#define HH 16
#define DD 64
#define MM (BB*TT)          // 8192
#define NQKV (3*CC)         // 3072

// Scratch: [B,H,T,D] layouts, 32MB each
__device__ float g_Q[BB*HH*TT*DD];
__device__ float g_K[BB*HH*TT*DD];
__device__ float g_V[BB*HH*TT*DD];
__device__ float g_Oa[BB*HH*TT*DD];

// ---------------------------------------------------------------------------
// Kernel 1: QKV GEMM  qkv[m,n] = sum_k X[m,k]*W[n,k], scatter into Q/K/V [B,H,T,D]
// 128x128 tile, BK=16, 256 threads, 8x8 micro-tile.
// ---------------------------------------------------------------------------
__global__ __launch_bounds__(256) void qkv_gemm_kernel(
    const float* __restrict__ X, const float* __restrict__ W)
{
    __shared__ float As[16][132];   // [k][m] transposed
    __shared__ float Bs[16][132];   // [k][n] transposed

    const int tid = threadIdx.x;
    const int m0 = blockIdx.y * 128;
    const int n0 = blockIdx.x * 128;
    const int ty = tid >> 4, tx = tid & 15;

    float acc[8][8];
    #pragma unroll
    for (int i = 0; i < 8; i++)
        #pragma unroll
        for (int j = 0; j < 8; j++) acc[i][j] = 0.0f;

    for (int k0 = 0; k0 < CC; k0 += 16) {
        #pragma unroll
        for (int l = 0; l < 2; l++) {
            int idx = l * 256 + tid;        // float4 slot, 0..511
            int row = idx >> 2;             // 128 rows, 4 float4/row
            int c4  = (idx & 3) * 4;
            float4 a = *(const float4*)(X + (size_t)(m0 + row) * CC + k0 + c4);
            As[c4+0][row] = a.x; As[c4+1][row] = a.y;
            As[c4+2][row] = a.z; As[c4+3][row] = a.w;
            float4 b = *(const float4*)(W + (size_t)(n0 + row) * CC + k0 + c4);
            Bs[c4+0][row] = b.x; Bs[c4+1][row] = b.y;
            Bs[c4+2][row] = b.z; Bs[c4+3][row] = b.w;
        }
        __syncthreads();
        #pragma unroll
        for (int k = 0; k < 16; k++) {
            float a[8], b[8];
            *(float4*)&a[0] = *(const float4*)&As[k][ty*8];
            *(float4*)&a[4] = *(const float4*)&As[k][ty*8+4];
            *(float4*)&b[0] = *(const float4*)&Bs[k][tx*8];
            *(float4*)&b[4] = *(const float4*)&Bs[k][tx*8+4];
            #pragma unroll
            for (int i = 0; i < 8; i++)
                #pragma unroll
                for (int j = 0; j < 8; j++)
                    acc[i][j] += a[i] * b[j];
        }
        __syncthreads();
    }

    // Scatter: n in [n0, n0+128); which tensor is constant per block (128 | 1024)
    const int which = n0 >> 10;
    float* dst = (which == 0) ? g_Q : ((which == 1) ? g_K : g_V);
    #pragma unroll
    for (int i = 0; i < 8; i++) {
        int m = m0 + ty*8 + i;
        int b = m >> 11, t = m & 2047;
        #pragma unroll
        for (int j = 0; j < 8; j += 4) {
            int n = n0 + tx*8 + j;
            int o = n & 1023;
            int h = o >> 6, d = o & 63;
            float4 v = make_float4(acc[i][j], acc[i][j+1], acc[i][j+2], acc[i][j+3]);
            *(float4*)(dst + ((size_t)(b*HH + h) * TT + t) * DD + d) = v;
        }
    }
}

// ---------------------------------------------------------------------------
// Kernel 2: Flash attention (causal), fp32.
// Block: 128 queries of one (b,h). K-tiles of 64. 256 threads.
// S frag: rows ty*8+i (q), cols tx*4+j (k). Out frag: rows ty*8+i, dims tx*4+j.
// Row stats replicated across the 16 threads of each row via butterfly shuffle.
// ---------------------------------------------------------------------------
#define QTILE 128
#define KTILE 64

struct AttnSmem {
    float QsT[64][132];     // [d][q]
    float KsT[64][68];      // [d][c]
    float Vs[64][68];       // [c][d]
    float Ps[128][65];      // [q][c]
};

__global__ __launch_bounds__(256) void attn_kernel()
{
    extern __shared__ char smem_raw[];
    AttnSmem& s = *(AttnSmem*)smem_raw;

    const int tid = threadIdx.x;
    const int ty = tid >> 4, tx = tid & 15;
    const int bh = blockIdx.y;
    const int q0 = blockIdx.x * QTILE;

    const float* Qb = g_Q + (size_t)bh * TT * DD;
    const float* Kb = g_K + (size_t)bh * TT * DD;
    const float* Vb = g_V + (size_t)bh * TT * DD;

    // Load Q tile transposed: 128x64 = 2048 float4, 8 per thread
    #pragma unroll
    for (int l = 0; l < 8; l++) {
        int idx = l * 256 + tid;
        int r  = idx >> 4;
        int d4 = (idx & 15) * 4;
        float4 v = *(const float4*)(Qb + (size_t)(q0 + r) * DD + d4);
        s.QsT[d4+0][r] = v.x; s.QsT[d4+1][r] = v.y;
        s.QsT[d4+2][r] = v.z; s.QsT[d4+3][r] = v.w;
    }

    float m_run[8], l_run[8], o_acc[8][4];
    #pragma unroll
    for (int i = 0; i < 8; i++) {
        m_run[i] = -1e30f; l_run[i] = 0.0f;
        #pragma unroll
        for (int j = 0; j < 4; j++) o_acc[i][j] = 0.0f;
    }

    const int nk = q0 / KTILE + 2;   // keys 0 .. q0+127
    for (int kt = 0; kt < nk; kt++) {
        const int k0 = kt * KTILE;
        __syncthreads();   // protect Ks/Vs/Ps still being read by prev iter

        // Load K,V tiles (64x64 each): 1024 float4 each, 4 per thread
        #pragma unroll
        for (int l = 0; l < 4; l++) {
            int idx = l * 256 + tid;
            int c  = idx >> 4;
            int d4 = (idx & 15) * 4;
            float4 kv = *(const float4*)(Kb + (size_t)(k0 + c) * DD + d4);
            s.KsT[d4+0][c] = kv.x; s.KsT[d4+1][c] = kv.y;
            s.KsT[d4+2][c] = kv.z; s.KsT[d4+3][c] = kv.w;
            float4 vv = *(const float4*)(Vb + (size_t)(k0 + c) * DD + d4);
            *(float4*)&s.Vs[c][d4] = vv;
        }
        __syncthreads();

        // S = scale * Q K^T
        float sc[8][4];
        #pragma unroll
        for (int i = 0; i < 8; i++)
            #pragma unroll
            for (int j = 0; j < 4; j++) sc[i][j] = 0.0f;

        #pragma unroll 8
        for (int d = 0; d < 64; d++) {
            float a[8], b[4];
            *(float4*)&a[0] = *(const float4*)&s.QsT[d][ty*8];
            *(float4*)&a[4] = *(const float4*)&s.QsT[d][ty*8+4];
            *(float4*)&b[0] = *(const float4*)&s.KsT[d][tx*4];
            #pragma unroll
            for (int i = 0; i < 8; i++)
                #pragma unroll
                for (int j = 0; j < 4; j++)
                    sc[i][j] += a[i] * b[j];
        }

        // scale + causal mask
        #pragma unroll
        for (int i = 0; i < 8; i++) {
            int qg = q0 + ty*8 + i;
            #pragma unroll
            for (int j = 0; j < 4; j++) {
                int kg = k0 + tx*4 + j;
                float v = sc[i][j] * 0.125f;
                sc[i][j] = (kg > qg) ? -1e30f : v;
            }
        }

        // online softmax update
        #pragma unroll
        for (int i = 0; i < 8; i++) {
            float tm = fmaxf(fmaxf(sc[i][0], sc[i][1]), fmaxf(sc[i][2], sc[i][3]));
            #pragma unroll
            for (int off = 1; off < 16; off <<= 1)
                tm = fmaxf(tm, __shfl_xor_sync(0xffffffffu, tm, off));
            float mnew = fmaxf(m_run[i], tm);
            float alpha = __expf(m_run[i] - mnew);
            m_run[i] = mnew;

            float rs = 0.0f;
            #pragma unroll
            for (int j = 0; j < 4; j++) {
                float p = __expf(sc[i][j] - mnew);
                sc[i][j] = p;
                rs += p;
            }
            #pragma unroll
            for (int off = 1; off < 16; off <<= 1)
                rs += __shfl_xor_sync(0xffffffffu, rs, off);
            l_run[i] = l_run[i] * alpha + rs;

            #pragma unroll
            for (int j = 0; j < 4; j++) {
                o_acc[i][j] *= alpha;
                s.Ps[ty*8 + i][tx*4 + j] = sc[i][j];
            }
        }
        __syncthreads();

        // O += P @ V
        #pragma unroll 8
        for (int c = 0; c < 64; c++) {
            float b[4];
            *(float4*)&b[0] = *(const float4*)&s.Vs[c][tx*4];
            #pragma unroll
            for (int i = 0; i < 8; i++) {
                float p = s.Ps[ty*8 + i][c];
                #pragma unroll
                for (int j = 0; j < 4; j++)
                    o_acc[i][j] += p * b[j];
            }
        }
    }

    // epilogue: normalize, write [B,H,T,D]
    #pragma unroll
    for (int i = 0; i < 8; i++) {
        float inv = 1.0f / l_run[i];
        int r = q0 + ty*8 + i;
        float4 v = make_float4(o_acc[i][0]*inv, o_acc[i][1]*inv,
                               o_acc[i][2]*inv, o_acc[i][3]*inv);
        *(float4*)(g_Oa + ((size_t)bh * TT + r) * DD + tx*4) = v;
    }
}

// ---------------------------------------------------------------------------
// Kernel 3: output projection Y[m,n] = sum_c A[m,c]*Wp[n,c]
// A gathered from g_Oa [B,H,T,D] with c = h*64+d. Same 128x128x16 tiling.
// ---------------------------------------------------------------------------
__global__ __launch_bounds__(256) void proj_gemm_kernel(
    const float* __restrict__ Wp, float* __restrict__ Y)
{
    __shared__ float As[16][132];
    __shared__ float Bs[16][132];

    const int tid = threadIdx.x;
    const int m0 = blockIdx.y * 128;
    const int n0 = blockIdx.x * 128;
    const int ty = tid >> 4, tx = tid & 15;

    float acc[8][8];
    #pragma unroll
    for (int i = 0; i < 8; i++)
        #pragma unroll
        for (int j = 0; j < 8; j++) acc[i][j] = 0.0f;

    for (int k0 = 0; k0 < CC; k0 += 16) {
        #pragma unroll
        for (int l = 0; l < 2; l++) {
            int idx = l * 256 + tid;
            int row = idx >> 2;
            int c4  = (idx & 3) * 4;
            int m = m0 + row;
            int b = m >> 11, t = m & 2047;
            int c = k0 + c4;
            int h = c >> 6, d = c & 63;     // 4-float chunk stays within one head
            float4 a = *(const float4*)(g_Oa + ((size_t)(b*HH + h) * TT + t) * DD + d);
            As[c4+0][row] = a.x; As[c4+1][row] = a.y;
            As[c4+2][row] = a.z; As[c4+3][row] = a.w;
            float4 w = *(const float4*)(Wp + (size_t)(n0 + row) * CC + k0 + c4);
            Bs[c4+0][row] = w.x; Bs[c4+1][row] = w.y;
            Bs[c4+2][row] = w.z; Bs[c4+3][row] = w.w;
        }
        __syncthreads();
        #pragma unroll
        for (int k = 0; k < 16; k++) {
            float a[8], b[8];
            *(float4*)&a[0] = *(const float4*)&As[k][ty*8];
            *(float4*)&a[4] = *(const float4*)&As[k][ty*8+4];
            *(float4*)&b[0] = *(const float4*)&Bs[k][tx*8];
            *(float4*)&b[4] = *(const float4*)&Bs[k][tx*8+4];
            #pragma unroll
            for (int i = 0; i < 8; i++)
                #pragma unroll
                for (int j = 0; j < 8; j++)
                    acc[i][j] += a[i] * b[j];
        }
        __syncthreads();
    }

    #pragma unroll
    for (int i = 0; i < 8; i++) {
        int m = m0 + ty*8 + i;
        #pragma unroll
        for (int j = 0; j < 8; j += 4) {
            int n = n0 + tx*8 + j;
            float4 v = make_float4(acc[i][j], acc[i][j+1], acc[i][j+2], acc[i][j+3]);
            *(float4*)(Y + (size_t)m * CC + n) = v;
        }
    }
}

// ---------------------------------------------------------------------------
extern "C" void kernel_launch(void* const* d_in, const int* in_sizes, int n_in,
                              void* d_out, int out_size)
{
    const float* x     = (const float*)d_in[0];   // [4,2048,1024]
    const float* wqkv  = (const float*)d_in[1];   // [3072,1024]
    const float* wproj = (const float*)d_in[2];   // [1024,1024]
    float* out = (float*)d_out;                   // [4,2048,1024]

    // Idempotent, host-side, not a stream op — capture-safe.
    cudaFuncSetAttribute((const void*)attn_kernel,
                         cudaFuncAttributeMaxDynamicSharedMemorySize,
                         (int)sizeof(AttnSmem));

    qkv_gemm_kernel<<<dim3(NQKV/128, MM/128), 256>>>(x, wqkv);
    attn_kernel<<<dim3(TT/QTILE, BB*HH), 256, sizeof(AttnSmem)>>>();
    proj_gemm_kernel<<<dim3(CC/128, MM/128), 256>>>(wproj, out);
}

// round 3
// speedup vs baseline: 1.3737x; 1.3737x over previous
#include <cuda_runtime.h>
#include <cuda_bf16.h>
#include <cstdint>
#include <math.h>

// Problem constants
#define BB 4
#define TT 2048
#define CC 1024
#define HH 16
#define DD 64
#define MM (BB*TT)          // 8192
#define NQKV (3*CC)         // 3072

// ---------------------------------------------------------------------------
// Scratch (__device__ globals; no allocation allowed)
// ---------------------------------------------------------------------------
__device__ float g_Q[BB*HH*TT*DD];
__device__ float g_K[BB*HH*TT*DD];
__device__ float g_V[BB*HH*TT*DD];

__device__ __nv_bfloat16 g_Xhi[MM*CC],  g_Xlo[MM*CC];      // x split
__device__ __nv_bfloat16 g_Wqhi[NQKV*CC], g_Wqlo[NQKV*CC]; // w_qkv split
__device__ __nv_bfloat16 g_Wphi[CC*CC], g_Wplo[CC*CC];     // w_proj split
__device__ __nv_bfloat16 g_Ohi[MM*CC],  g_Olo[MM*CC];      // attn out split

// ---------------------------------------------------------------------------
// helpers
// ---------------------------------------------------------------------------
__device__ __forceinline__ uint32_t smem_u32(const void* p) {
    uint32_t a;
    asm("{ .reg .u64 t; cvta.to.shared.u64 t, %1; cvt.u32.u64 %0, t; }" : "=r"(a) : "l"(p));
    return a;
}
__device__ __forceinline__ void ldsm_x4(uint32_t& r0, uint32_t& r1, uint32_t& r2,
                                        uint32_t& r3, uint32_t addr) {
    asm volatile("ldmatrix.sync.aligned.m8n8.x4.shared.b16 {%0,%1,%2,%3}, [%4];"
                 : "=r"(r0), "=r"(r1), "=r"(r2), "=r"(r3) : "r"(addr));
}
__device__ __forceinline__ void mma_bf16(float* c, const uint32_t* a, const uint32_t* b) {
    asm volatile("mma.sync.aligned.m16n8k16.row.col.f32.bf16.bf16.f32 "
                 "{%0,%1,%2,%3}, {%4,%5,%6,%7}, {%8,%9}, {%0,%1,%2,%3};"
                 : "+f"(c[0]), "+f"(c[1]), "+f"(c[2]), "+f"(c[3])
                 : "r"(a[0]), "r"(a[1]), "r"(a[2]), "r"(a[3]), "r"(b[0]), "r"(b[1]));
}
__device__ __forceinline__ void split_f32(float x, __nv_bfloat16& hi, __nv_bfloat16& lo) {
    hi = __float2bfloat16(x);
    lo = __float2bfloat16(x - __bfloat162float(hi));
}

// ---------------------------------------------------------------------------
// fp32 -> (hi,lo) bf16 split, float4-vectorized
// ---------------------------------------------------------------------------
__global__ __launch_bounds__(256) void split_kernel(const float* __restrict__ src,
                                                    __nv_bfloat16* __restrict__ hi,
                                                    __nv_bfloat16* __restrict__ lo, int n4)
{
    int i = blockIdx.x * blockDim.x + threadIdx.x;
    if (i >= n4) return;
    float4 v = ((const float4*)src)[i];
    __nv_bfloat16 h[4], l[4];
    split_f32(v.x, h[0], l[0]); split_f32(v.y, h[1], l[1]);
    split_f32(v.z, h[2], l[2]); split_f32(v.w, h[3], l[3]);
    ((__nv_bfloat162*)hi)[i*2+0] = __nv_bfloat162(h[0], h[1]);
    ((__nv_bfloat162*)hi)[i*2+1] = __nv_bfloat162(h[2], h[3]);
    ((__nv_bfloat162*)lo)[i*2+0] = __nv_bfloat162(l[0], l[1]);
    ((__nv_bfloat162*)lo)[i*2+1] = __nv_bfloat162(l[2], l[3]);
}

// ---------------------------------------------------------------------------
// HMMA split-bf16 GEMM: C[m,n] = sum_k A[m,k]*B[n,k]  (fp32-equivalent)
// 128x128 CTA tile, BK=32, 8 warps (2x4), warp tile 64x32, m16n8k16 mma.
// MODE 0: scatter to g_Q/g_K/g_V [B,H,T,D].  MODE 1: fp32 out [M,1024].
// ---------------------------------------------------------------------------
#define BK 32
#define LDSR 40                    // row stride in bf16 (32 + 8 pad = 80B, conflict-free)
#define TILE_ELE (128*LDSR)        // 5120 bf16 per tile
#define STAGE_ELE (4*TILE_ELE)     // Ahi,Alo,Bhi,Blo
#define GEMM_SMEM_BYTES (2*STAGE_ELE*2)   // 81920 B

template<int MODE>
__global__ __launch_bounds__(256, 1) void mma_gemm_kernel(
    const __nv_bfloat16* __restrict__ Ahi, const __nv_bfloat16* __restrict__ Alo,
    const __nv_bfloat16* __restrict__ Bhi, const __nv_bfloat16* __restrict__ Blo,
    float* __restrict__ out)
{
    extern __shared__ __nv_bfloat16 sm[];
    const int tid = threadIdx.x;
    const int lane = tid & 31, wid = tid >> 5;
    const int wm = (wid >> 2) * 64;        // 0 | 64
    const int wn = (wid & 3) * 32;         // 0,32,64,96
    const int n0 = blockIdx.x * 128;
    const int m0 = blockIdx.y * 128;

    const __nv_bfloat16* srcs[4] = {
        Ahi + (size_t)m0 * CC, Alo + (size_t)m0 * CC,
        Bhi + (size_t)n0 * CC, Blo + (size_t)n0 * CC };

    // per-thread load slots: idx = l*256+tid -> row=idx>>2, c=idx&3 (uint4 = 8 bf16)
    const int r_[2] = { tid >> 2, 64 + (tid >> 2) };
    const int c_ = (tid & 3) * 8;

    float acc[4][4][4];
    #pragma unroll
    for (int a = 0; a < 4; a++)
        #pragma unroll
        for (int b = 0; b < 4; b++)
            #pragma unroll
            for (int c = 0; c < 4; c++) acc[a][b][c] = 0.0f;

    // ldmatrix lane addressing offsets
    const int a_m = ((lane >> 3) & 1) * 8 + (lane & 7);
    const int a_k = (lane >> 4) * 8;
    const int b_n = (lane >> 4) * 8 + (lane & 7);
    const int b_k = ((lane >> 3) & 1) * 8;

    const int NCH = CC / BK;   // 32

    // preload stage 0
    #pragma unroll
    for (int t = 0; t < 4; t++)
        #pragma unroll
        for (int l = 0; l < 2; l++)
            *(uint4*)(sm + t * TILE_ELE + r_[l] * LDSR + c_) =
                *(const uint4*)(srcs[t] + (size_t)r_[l] * CC + c_);
    __syncthreads();

    for (int ch = 0; ch < NCH; ch++) {
        const __nv_bfloat16* buf = sm + (ch & 1) * STAGE_ELE;

        // prefetch next chunk gmem -> regs
        uint4 pf[4][2];
        if (ch + 1 < NCH) {
            const int k0n = (ch + 1) * BK;
            #pragma unroll
            for (int t = 0; t < 4; t++)
                #pragma unroll
                for (int l = 0; l < 2; l++)
                    pf[t][l] = *(const uint4*)(srcs[t] + (size_t)r_[l] * CC + k0n + c_);
        }

        // compute this chunk: two k16 sub-steps
        #pragma unroll
        for (int kk = 0; kk < BK; kk += 16) {
            uint32_t aH[4][4], aL[4][4], bH[2][4], bL[2][4];
            #pragma unroll
            for (int mi = 0; mi < 4; mi++) {
                const int m = wm + mi * 16 + a_m;
                uint32_t ad = smem_u32(buf + m * LDSR + kk + a_k);
                ldsm_x4(aH[mi][0], aH[mi][1], aH[mi][2], aH[mi][3], ad);
                ldsm_x4(aL[mi][0], aL[mi][1], aL[mi][2], aL[mi][3], ad + TILE_ELE * 2);
            }
            #pragma unroll
            for (int ni = 0; ni < 2; ni++) {
                const int n = wn + ni * 16 + b_n;
                uint32_t bd = smem_u32(buf + 2 * TILE_ELE + n * LDSR + kk + b_k);
                ldsm_x4(bH[ni][0], bH[ni][1], bH[ni][2], bH[ni][3], bd);
                ldsm_x4(bL[ni][0], bL[ni][1], bL[ni][2], bL[ni][3], bd + TILE_ELE * 2);
            }
            #pragma unroll
            for (int mi = 0; mi < 4; mi++)
                #pragma unroll
                for (int nj = 0; nj < 4; nj++) {
                    uint32_t bh[2] = { bH[nj >> 1][(nj & 1) * 2], bH[nj >> 1][(nj & 1) * 2 + 1] };
                    uint32_t bl[2] = { bL[nj >> 1][(nj & 1) * 2], bL[nj >> 1][(nj & 1) * 2 + 1] };
                    mma_bf16(acc[mi][nj], aH[mi], bh);
                    mma_bf16(acc[mi][nj], aH[mi], bl);
                    mma_bf16(acc[mi][nj], aL[mi], bh);
                }
        }

        __syncthreads();
        if (ch + 1 < NCH) {
            __nv_bfloat16* nb = sm + ((ch + 1) & 1) * STAGE_ELE;
            #pragma unroll
            for (int t = 0; t < 4; t++)
                #pragma unroll
                for (int l = 0; l < 2; l++)
                    *(uint4*)(nb + t * TILE_ELE + r_[l] * LDSR + c_) = pf[t][l];
            __syncthreads();
        }
    }

    // epilogue
    #pragma unroll
    for (int mi = 0; mi < 4; mi++) {
        #pragma unroll
        for (int nj = 0; nj < 4; nj++) {
            const int row0 = m0 + wm + mi * 16 + (lane >> 2);
            const int col  = n0 + wn + nj * 8 + (lane & 3) * 2;
            #pragma unroll
            for (int h = 0; h < 2; h++) {
                const int row = row0 + h * 8;
                float2 v = make_float2(acc[mi][nj][h * 2], acc[mi][nj][h * 2 + 1]);
                if (MODE == 0) {
                    const int b = row >> 11, t = row & 2047;
                    const int which = col >> 10;
                    float* dst = (which == 0) ? g_Q : ((which == 1) ? g_K : g_V);
                    const int o = col & 1023, hd = o >> 6, d = o & 63;
                    *(float2*)(dst + ((size_t)(b * HH + hd) * TT + t) * DD + d) = v;
                } else {
                    *(float2*)(out + (size_t)row * CC + col) = v;
                }
            }
        }
    }
}

// ---------------------------------------------------------------------------
// Flash attention (causal), fp32 SIMT. Writes (hi,lo) bf16 in [B*T, C].
// ---------------------------------------------------------------------------
#define QTILE 128
#define KTILE 64

struct AttnSmem {
    float QsT[64][132];
    float KsT[64][68];
    float Vs[64][68];
    float Ps[128][65];
};

__global__ __launch_bounds__(256) void attn_kernel()
{
    extern __shared__ char smem_raw[];
    AttnSmem& s = *(AttnSmem*)smem_raw;

    const int tid = threadIdx.x;
    const int ty = tid >> 4, tx = tid & 15;
    const int bh = blockIdx.y;
    const int q0 = blockIdx.x * QTILE;

    const float* Qb = g_Q + (size_t)bh * TT * DD;
    const float* Kb = g_K + (size_t)bh * TT * DD;
    const float* Vb = g_V + (size_t)bh * TT * DD;

    #pragma unroll
    for (int l = 0; l < 8; l++) {
        int idx = l * 256 + tid;
        int r  = idx >> 4;
        int d4 = (idx & 15) * 4;
        float4 v = *(const float4*)(Qb + (size_t)(q0 + r) * DD + d4);
        s.QsT[d4+0][r] = v.x; s.QsT[d4+1][r] = v.y;
        s.QsT[d4+2][r] = v.z; s.QsT[d4+3][r] = v.w;
    }

    float m_run[8], l_run[8], o_acc[8][4];
    #pragma unroll
    for (int i = 0; i < 8; i++) {
        m_run[i] = -1e30f; l_run[i] = 0.0f;
        #pragma unroll
        for (int j = 0; j < 4; j++) o_acc[i][j] = 0.0f;
    }

    const int nk = q0 / KTILE + 2;
    for (int kt = 0; kt < nk; kt++) {
        const int k0 = kt * KTILE;
        __syncthreads();

        #pragma unroll
        for (int l = 0; l < 4; l++) {
            int idx = l * 256 + tid;
            int c  = idx >> 4;
            int d4 = (idx & 15) * 4;
            float4 kv = *(const float4*)(Kb + (size_t)(k0 + c) * DD + d4);
            s.KsT[d4+0][c] = kv.x; s.KsT[d4+1][c] = kv.y;
            s.KsT[d4+2][c] = kv.z; s.KsT[d4+3][c] = kv.w;
            float4 vv = *(const float4*)(Vb + (size_t)(k0 + c) * DD + d4);
            *(float4*)&s.Vs[c][d4] = vv;
        }
        __syncthreads();

        float sc[8][4];
        #pragma unroll
        for (int i = 0; i < 8; i++)
            #pragma unroll
            for (int j = 0; j < 4; j++) sc[i][j] = 0.0f;

        #pragma unroll 8
        for (int d = 0; d < 64; d++) {
            float a[8], b[4];
            *(float4*)&a[0] = *(const float4*)&s.QsT[d][ty*8];
            *(float4*)&a[4] = *(const float4*)&s.QsT[d][ty*8+4];
            *(float4*)&b[0] = *(const float4*)&s.KsT[d][tx*4];
            #pragma unroll
            for (int i = 0; i < 8; i++)
                #pragma unroll
                for (int j = 0; j < 4; j++)
                    sc[i][j] += a[i] * b[j];
        }

        #pragma unroll
        for (int i = 0; i < 8; i++) {
            int qg = q0 + ty*8 + i;
            #pragma unroll
            for (int j = 0; j < 4; j++) {
                int kg = k0 + tx*4 + j;
                float v = sc[i][j] * 0.125f;
                sc[i][j] = (kg > qg) ? -1e30f : v;
            }
        }

        #pragma unroll
        for (int i = 0; i < 8; i++) {
            float tm = fmaxf(fmaxf(sc[i][0], sc[i][1]), fmaxf(sc[i][2], sc[i][3]));
            #pragma unroll
            for (int off = 1; off < 16; off <<= 1)
                tm = fmaxf(tm, __shfl_xor_sync(0xffffffffu, tm, off));
            float mnew = fmaxf(m_run[i], tm);
            float alpha = __expf(m_run[i] - mnew);
            m_run[i] = mnew;

            float rs = 0.0f;
            #pragma unroll
            for (int j = 0; j < 4; j++) {
                float p = __expf(sc[i][j] - mnew);
                sc[i][j] = p;
                rs += p;
            }
            #pragma unroll
            for (int off = 1; off < 16; off <<= 1)
                rs += __shfl_xor_sync(0xffffffffu, rs, off);
            l_run[i] = l_run[i] * alpha + rs;

            #pragma unroll
            for (int j = 0; j < 4; j++) {
                o_acc[i][j] *= alpha;
                s.Ps[ty*8 + i][tx*4 + j] = sc[i][j];
            }
        }
        __syncthreads();

        #pragma unroll 8
        for (int c = 0; c < 64; c++) {
            float b[4];
            *(float4*)&b[0] = *(const float4*)&s.Vs[c][tx*4];
            #pragma unroll
            for (int i = 0; i < 8; i++) {
                float p = s.Ps[ty*8 + i][c];
                #pragma unroll
                for (int j = 0; j < 4; j++)
                    o_acc[i][j] += p * b[j];
            }
        }
    }

    const int b = bh >> 4, h = bh & 15;
    #pragma unroll
    for (int i = 0; i < 8; i++) {
        float inv = 1.0f / l_run[i];
        int r = q0 + ty*8 + i;
        size_t off = (size_t)(b * TT + r) * CC + h * DD + tx * 4;
        __nv_bfloat16 hi[4], lo[4];
        #pragma unroll
        for (int j = 0; j < 4; j++) split_f32(o_acc[i][j] * inv, hi[j], lo[j]);
        *(__nv_bfloat162*)(g_Ohi + off)     = __nv_bfloat162(hi[0], hi[1]);
        *(__nv_bfloat162*)(g_Ohi + off + 2) = __nv_bfloat162(hi[2], hi[3]);
        *(__nv_bfloat162*)(g_Olo + off)     = __nv_bfloat162(lo[0], lo[1]);
        *(__nv_bfloat162*)(g_Olo + off + 2) = __nv_bfloat162(lo[2], lo[3]);
    }
}

// ---------------------------------------------------------------------------
extern "C" void kernel_launch(void* const* d_in, const int* in_sizes, int n_in,
                              void* d_out, int out_size)
{
    const float* x     = (const float*)d_in[0];   // [4,2048,1024]
    const float* wqkv  = (const float*)d_in[1];   // [3072,1024]
    const float* wproj = (const float*)d_in[2];   // [1024,1024]
    float* out = (float*)d_out;                   // [4,2048,1024]

    cudaFuncSetAttribute((const void*)attn_kernel,
                         cudaFuncAttributeMaxDynamicSharedMemorySize, (int)sizeof(AttnSmem));
    cudaFuncSetAttribute((const void*)mma_gemm_kernel<0>,
                         cudaFuncAttributeMaxDynamicSharedMemorySize, GEMM_SMEM_BYTES);
    cudaFuncSetAttribute((const void*)mma_gemm_kernel<1>,
                         cudaFuncAttributeMaxDynamicSharedMemorySize, GEMM_SMEM_BYTES);

    __nv_bfloat16 *xhi, *xlo, *wqhi, *wqlo, *wphi, *wplo, *ohi, *olo;
    cudaGetSymbolAddress((void**)&xhi,  g_Xhi);  cudaGetSymbolAddress((void**)&xlo,  g_Xlo);
    cudaGetSymbolAddress((void**)&wqhi, g_Wqhi); cudaGetSymbolAddress((void**)&wqlo, g_Wqlo);
    cudaGetSymbolAddress((void**)&wphi, g_Wphi); cudaGetSymbolAddress((void**)&wplo, g_Wplo);
    cudaGetSymbolAddress((void**)&ohi,  g_Ohi);  cudaGetSymbolAddress((void**)&olo,  g_Olo);

    split_kernel<<<(MM*CC/4 + 255)/256, 256>>>(x, xhi, xlo, MM*CC/4);
    split_kernel<<<(NQKV*CC/4 + 255)/256, 256>>>(wqkv, wqhi, wqlo, NQKV*CC/4);
    split_kernel<<<(CC*CC/4 + 255)/256, 256>>>(wproj, wphi, wplo, CC*CC/4);

    mma_gemm_kernel<0><<<dim3(NQKV/128, MM/128), 256, GEMM_SMEM_BYTES>>>(
        xhi, xlo, wqhi, wqlo, nullptr);

    attn_kernel<<<dim3(TT/QTILE, BB*HH), 256, sizeof(AttnSmem)>>>();

    mma_gemm_kernel<1><<<dim3(CC/128, MM/128), 256, GEMM_SMEM_BYTES>>>(
        ohi, olo, wphi, wplo, out);
}

// round 4
// speedup vs baseline: 2.1481x; 1.5638x over previous
#include <cuda_runtime.h>
#include <cuda_bf16.h>
#include <cstdint>
#include <math.h>

// Problem constants
#define BB 4
#define TT 2048
#define CC 1024
#define HH 16
#define DD 64
#define MM (BB*TT)          // 8192
#define NQKV (3*CC)         // 3072

// ---------------------------------------------------------------------------
// Scratch (__device__ globals; no allocation allowed)
// ---------------------------------------------------------------------------
__device__ __nv_bfloat16 g_Qhi[BB*HH*TT*DD], g_Qlo[BB*HH*TT*DD];
__device__ __nv_bfloat16 g_Khi[BB*HH*TT*DD], g_Klo[BB*HH*TT*DD];
__device__ __nv_bfloat16 g_Vhi[BB*HH*TT*DD], g_Vlo[BB*HH*TT*DD];

__device__ __nv_bfloat16 g_Xhi[MM*CC],  g_Xlo[MM*CC];      // x split
__device__ __nv_bfloat16 g_Wqhi[NQKV*CC], g_Wqlo[NQKV*CC]; // w_qkv split
__device__ __nv_bfloat16 g_Wphi[CC*CC], g_Wplo[CC*CC];     // w_proj split
__device__ __nv_bfloat16 g_Ohi[MM*CC],  g_Olo[MM*CC];      // attn out split

// ---------------------------------------------------------------------------
// helpers
// ---------------------------------------------------------------------------
__device__ __forceinline__ uint32_t smem_u32(const void* p) {
    uint32_t a;
    asm("{ .reg .u64 t; cvta.to.shared.u64 t, %1; cvt.u32.u64 %0, t; }" : "=r"(a) : "l"(p));
    return a;
}
__device__ __forceinline__ void ldsm_x4(uint32_t& r0, uint32_t& r1, uint32_t& r2,
                                        uint32_t& r3, uint32_t addr) {
    asm volatile("ldmatrix.sync.aligned.m8n8.x4.shared.b16 {%0,%1,%2,%3}, [%4];"
                 : "=r"(r0), "=r"(r1), "=r"(r2), "=r"(r3) : "r"(addr));
}
__device__ __forceinline__ void mma_bf16(float* c, const uint32_t* a, const uint32_t* b) {
    asm volatile("mma.sync.aligned.m16n8k16.row.col.f32.bf16.bf16.f32 "
                 "{%0,%1,%2,%3}, {%4,%5,%6,%7}, {%8,%9}, {%0,%1,%2,%3};"
                 : "+f"(c[0]), "+f"(c[1]), "+f"(c[2]), "+f"(c[3])
                 : "r"(a[0]), "r"(a[1]), "r"(a[2]), "r"(a[3]), "r"(b[0]), "r"(b[1]));
}
__device__ __forceinline__ void split_f32(float x, __nv_bfloat16& hi, __nv_bfloat16& lo) {
    hi = __float2bfloat16(x);
    lo = __float2bfloat16(x - __bfloat162float(hi));
}
__device__ __forceinline__ uint32_t pack2(__nv_bfloat16 a, __nv_bfloat16 b) {
    __nv_bfloat162 t(a, b);                 // a -> low half
    return *reinterpret_cast<uint32_t*>(&t);
}
// split two fp32 into packed (hi,lo) bf16x2 regs; element x goes to low half
__device__ __forceinline__ void pack_hilo(float x, float y, uint32_t& hi, uint32_t& lo) {
    __nv_bfloat16 hx, lx, hy, ly;
    split_f32(x, hx, lx); split_f32(y, hy, ly);
    hi = pack2(hx, hy); lo = pack2(lx, ly);
}

// ---------------------------------------------------------------------------
// fp32 -> (hi,lo) bf16 split, float4-vectorized
// ---------------------------------------------------------------------------
__global__ __launch_bounds__(256) void split_kernel(const float* __restrict__ src,
                                                    __nv_bfloat16* __restrict__ hi,
                                                    __nv_bfloat16* __restrict__ lo, int n4)
{
    int i = blockIdx.x * blockDim.x + threadIdx.x;
    if (i >= n4) return;
    float4 v = ((const float4*)src)[i];
    __nv_bfloat16 h[4], l[4];
    split_f32(v.x, h[0], l[0]); split_f32(v.y, h[1], l[1]);
    split_f32(v.z, h[2], l[2]); split_f32(v.w, h[3], l[3]);
    ((__nv_bfloat162*)hi)[i*2+0] = __nv_bfloat162(h[0], h[1]);
    ((__nv_bfloat162*)hi)[i*2+1] = __nv_bfloat162(h[2], h[3]);
    ((__nv_bfloat162*)lo)[i*2+0] = __nv_bfloat162(l[0], l[1]);
    ((__nv_bfloat162*)lo)[i*2+1] = __nv_bfloat162(l[2], l[3]);
}

// ---------------------------------------------------------------------------
// HMMA split-bf16 GEMM: C[m,n] = sum_k A[m,k]*B[n,k]
// MODE 0: split C to (hi,lo) bf16 and scatter to g_{Q,K,V}{hi,lo} [B,H,T,D]
//         (Q additionally scaled by 1/sqrt(64) = 0.125)
// MODE 1: fp32 out [M,1024]
// ---------------------------------------------------------------------------
#define BK 32
#define LDSR 40
#define TILE_ELE (128*LDSR)
#define STAGE_ELE (4*TILE_ELE)
#define GEMM_SMEM_BYTES (2*STAGE_ELE*2)   // 81920 B

template<int MODE>
__global__ __launch_bounds__(256, 1) void mma_gemm_kernel(
    const __nv_bfloat16* __restrict__ Ahi, const __nv_bfloat16* __restrict__ Alo,
    const __nv_bfloat16* __restrict__ Bhi, const __nv_bfloat16* __restrict__ Blo,
    float* __restrict__ out)
{
    extern __shared__ __nv_bfloat16 sm[];
    const int tid = threadIdx.x;
    const int lane = tid & 31, wid = tid >> 5;
    const int wm = (wid >> 2) * 64;
    const int wn = (wid & 3) * 32;
    const int n0 = blockIdx.x * 128;
    const int m0 = blockIdx.y * 128;

    const __nv_bfloat16* srcs[4] = {
        Ahi + (size_t)m0 * CC, Alo + (size_t)m0 * CC,
        Bhi + (size_t)n0 * CC, Blo + (size_t)n0 * CC };

    const int r_[2] = { tid >> 2, 64 + (tid >> 2) };
    const int c_ = (tid & 3) * 8;

    float acc[4][4][4];
    #pragma unroll
    for (int a = 0; a < 4; a++)
        #pragma unroll
        for (int b = 0; b < 4; b++)
            #pragma unroll
            for (int c = 0; c < 4; c++) acc[a][b][c] = 0.0f;

    const int a_m = ((lane >> 3) & 1) * 8 + (lane & 7);
    const int a_k = (lane >> 4) * 8;
    const int b_n = (lane >> 4) * 8 + (lane & 7);
    const int b_k = ((lane >> 3) & 1) * 8;

    const int NCH = CC / BK;

    #pragma unroll
    for (int t = 0; t < 4; t++)
        #pragma unroll
        for (int l = 0; l < 2; l++)
            *(uint4*)(sm + t * TILE_ELE + r_[l] * LDSR + c_) =
                *(const uint4*)(srcs[t] + (size_t)r_[l] * CC + c_);
    __syncthreads();

    for (int ch = 0; ch < NCH; ch++) {
        const __nv_bfloat16* buf = sm + (ch & 1) * STAGE_ELE;

        uint4 pf[4][2];
        if (ch + 1 < NCH) {
            const int k0n = (ch + 1) * BK;
            #pragma unroll
            for (int t = 0; t < 4; t++)
                #pragma unroll
                for (int l = 0; l < 2; l++)
                    pf[t][l] = *(const uint4*)(srcs[t] + (size_t)r_[l] * CC + k0n + c_);
        }

        #pragma unroll
        for (int kk = 0; kk < BK; kk += 16) {
            uint32_t aH[4][4], aL[4][4], bH[2][4], bL[2][4];
            #pragma unroll
            for (int mi = 0; mi < 4; mi++) {
                const int m = wm + mi * 16 + a_m;
                uint32_t ad = smem_u32(buf + m * LDSR + kk + a_k);
                ldsm_x4(aH[mi][0], aH[mi][1], aH[mi][2], aH[mi][3], ad);
                ldsm_x4(aL[mi][0], aL[mi][1], aL[mi][2], aL[mi][3], ad + TILE_ELE * 2);
            }
            #pragma unroll
            for (int ni = 0; ni < 2; ni++) {
                const int n = wn + ni * 16 + b_n;
                uint32_t bd = smem_u32(buf + 2 * TILE_ELE + n * LDSR + kk + b_k);
                ldsm_x4(bH[ni][0], bH[ni][1], bH[ni][2], bH[ni][3], bd);
                ldsm_x4(bL[ni][0], bL[ni][1], bL[ni][2], bL[ni][3], bd + TILE_ELE * 2);
            }
            #pragma unroll
            for (int mi = 0; mi < 4; mi++)
                #pragma unroll
                for (int nj = 0; nj < 4; nj++) {
                    uint32_t bh[2] = { bH[nj >> 1][(nj & 1) * 2], bH[nj >> 1][(nj & 1) * 2 + 1] };
                    uint32_t bl[2] = { bL[nj >> 1][(nj & 1) * 2], bL[nj >> 1][(nj & 1) * 2 + 1] };
                    mma_bf16(acc[mi][nj], aH[mi], bh);
                    mma_bf16(acc[mi][nj], aH[mi], bl);
                    mma_bf16(acc[mi][nj], aL[mi], bh);
                }
        }

        __syncthreads();
        if (ch + 1 < NCH) {
            __nv_bfloat16* nb = sm + ((ch + 1) & 1) * STAGE_ELE;
            #pragma unroll
            for (int t = 0; t < 4; t++)
                #pragma unroll
                for (int l = 0; l < 2; l++)
                    *(uint4*)(nb + t * TILE_ELE + r_[l] * LDSR + c_) = pf[t][l];
            __syncthreads();
        }
    }

    // epilogue
    if (MODE == 0) {
        const int which = n0 >> 10;      // constant per CTA
        __nv_bfloat16* dhi = (which == 0) ? g_Qhi : ((which == 1) ? g_Khi : g_Vhi);
        __nv_bfloat16* dlo = (which == 0) ? g_Qlo : ((which == 1) ? g_Klo : g_Vlo);
        const float scl = (which == 0) ? 0.125f : 1.0f;
        #pragma unroll
        for (int mi = 0; mi < 4; mi++)
            #pragma unroll
            for (int nj = 0; nj < 4; nj++) {
                const int row0 = m0 + wm + mi * 16 + (lane >> 2);
                const int col  = n0 + wn + nj * 8 + (lane & 3) * 2;
                const int o = col & 1023, hd = o >> 6, d = o & 63;
                #pragma unroll
                for (int h = 0; h < 2; h++) {
                    const int row = row0 + h * 8;
                    const int b = row >> 11, t = row & 2047;
                    uint32_t vh, vl;
                    pack_hilo(acc[mi][nj][h*2] * scl, acc[mi][nj][h*2+1] * scl, vh, vl);
                    size_t off = ((size_t)(b * HH + hd) * TT + t) * DD + d;
                    *(uint32_t*)(dhi + off) = vh;
                    *(uint32_t*)(dlo + off) = vl;
                }
            }
    } else {
        #pragma unroll
        for (int mi = 0; mi < 4; mi++)
            #pragma unroll
            for (int nj = 0; nj < 4; nj++) {
                const int row0 = m0 + wm + mi * 16 + (lane >> 2);
                const int col  = n0 + wn + nj * 8 + (lane & 3) * 2;
                #pragma unroll
                for (int h = 0; h < 2; h++) {
                    const int row = row0 + h * 8;
                    float2 v = make_float2(acc[mi][nj][h*2], acc[mi][nj][h*2+1]);
                    *(float2*)(out + (size_t)row * CC + col) = v;
                }
            }
    }
}

// ---------------------------------------------------------------------------
// Tensor-core flash attention (causal). 128 q-rows/CTA, KTILE=64, 8 warps.
// S = Q K^T (scale pre-folded into Q). Split-bf16, 3 passes per GEMM.
// Output written as (hi,lo) bf16 in [B*T, C].
// ---------------------------------------------------------------------------
#define AQT 128
#define AKT 64
#define ALD 72     // row pitch in bf16 (144 B = 9*16B -> ldmatrix conflict-free)

struct AttnSmem {
    __nv_bfloat16 Qhi[AQT*ALD], Qlo[AQT*ALD];
    __nv_bfloat16 Khi[AKT*ALD], Klo[AKT*ALD];
    __nv_bfloat16 VThi[DD*ALD], VTlo[DD*ALD];   // [d][key]
};
#define ATTN_SMEM_BYTES ((int)sizeof(AttnSmem))

__global__ __launch_bounds__(256, 1) void attn_mma_kernel()
{
    extern __shared__ char smraw[];
    AttnSmem& s = *(AttnSmem*)smraw;

    const int tid = threadIdx.x, lane = tid & 31, w = tid >> 5;
    const int bh = blockIdx.y;
    const int qi = gridDim.x - 1 - blockIdx.x;     // longest tiles first
    const int q0 = qi * AQT;
    const size_t base = (size_t)bh * TT * DD;
    const __nv_bfloat16 *Qh = g_Qhi + base, *Ql = g_Qlo + base;
    const __nv_bfloat16 *Kh = g_Khi + base, *Kl = g_Klo + base;
    const __nv_bfloat16 *Vh = g_Vhi + base, *Vl = g_Vlo + base;

    // ---- load Q tile (hi,lo) into smem ----
    #pragma unroll
    for (int l = 0; l < 4; l++) {
        int idx = l * 256 + tid;
        int r = idx >> 3, d0 = (idx & 7) * 8;
        *(uint4*)&s.Qhi[r * ALD + d0] = *(const uint4*)(Qh + (size_t)(q0 + r) * DD + d0);
        *(uint4*)&s.Qlo[r * ALD + d0] = *(const uint4*)(Ql + (size_t)(q0 + r) * DD + d0);
    }
    __syncthreads();

    const int a_m = ((lane >> 3) & 1) * 8 + (lane & 7);
    const int a_k = (lane >> 4) * 8;
    const int b_n = (lane >> 4) * 8 + (lane & 7);
    const int b_k = ((lane >> 3) & 1) * 8;

    // ---- Q fragments into registers (persist across K loop) ----
    uint32_t qh[4][4], ql[4][4];
    #pragma unroll
    for (int ks = 0; ks < 4; ks++) {
        uint32_t qa = smem_u32(&s.Qhi[(w * 16 + a_m) * ALD + ks * 16 + a_k]);
        ldsm_x4(qh[ks][0], qh[ks][1], qh[ks][2], qh[ks][3], qa);
        uint32_t qb = smem_u32(&s.Qlo[(w * 16 + a_m) * ALD + ks * 16 + a_k]);
        ldsm_x4(ql[ks][0], ql[ks][1], ql[ks][2], ql[ks][3], qb);
    }

    float oacc[8][4];
    #pragma unroll
    for (int i = 0; i < 8; i++)
        #pragma unroll
        for (int j = 0; j < 4; j++) oacc[i][j] = 0.0f;
    float mrun[2] = { -1e30f, -1e30f }, lsum[2] = { 0.0f, 0.0f };

    const int qrow = q0 + w * 16 + (lane >> 2);   // smaller of this thread's 2 rows
    const int nk = 2 * qi + 2;

    for (int kt = 0; kt < nk; kt++) {
        const int k0 = kt * AKT;
        __syncthreads();

        // ---- K tile (coalesced) ----
        #pragma unroll
        for (int l = 0; l < 2; l++) {
            int idx = l * 256 + tid;
            int key = idx >> 3, d0 = (idx & 7) * 8;
            *(uint4*)&s.Khi[key * ALD + d0] = *(const uint4*)(Kh + (size_t)(k0 + key) * DD + d0);
            *(uint4*)&s.Klo[key * ALD + d0] = *(const uint4*)(Kl + (size_t)(k0 + key) * DD + d0);
        }
        // ---- V tile transposed: VsT[d][key] ----
        #pragma unroll
        for (int l = 0; l < 2; l++) {
            int idx = l * 256 + tid;
            int key = idx & 63, d0 = (idx >> 6) * 8;
            uint4 v = *(const uint4*)(Vh + (size_t)(k0 + key) * DD + d0);
            __nv_bfloat16 tmp[8]; *(uint4*)tmp = v;
            #pragma unroll
            for (int j = 0; j < 8; j++) s.VThi[(d0 + j) * ALD + key] = tmp[j];
            uint4 v2 = *(const uint4*)(Vl + (size_t)(k0 + key) * DD + d0);
            *(uint4*)tmp = v2;
            #pragma unroll
            for (int j = 0; j < 8; j++) s.VTlo[(d0 + j) * ALD + key] = tmp[j];
        }
        __syncthreads();

        // ---- S = Q K^T (3-pass split) ----
        float sacc[8][4];
        #pragma unroll
        for (int i = 0; i < 8; i++)
            #pragma unroll
            for (int j = 0; j < 4; j++) sacc[i][j] = 0.0f;

        #pragma unroll
        for (int nbp = 0; nbp < 4; nbp++) {
            #pragma unroll
            for (int ks = 0; ks < 4; ks++) {
                uint32_t kh4[4], kl4[4];
                uint32_t ka = smem_u32(&s.Khi[(nbp * 16 + b_n) * ALD + ks * 16 + b_k]);
                ldsm_x4(kh4[0], kh4[1], kh4[2], kh4[3], ka);
                uint32_t kb = smem_u32(&s.Klo[(nbp * 16 + b_n) * ALD + ks * 16 + b_k]);
                ldsm_x4(kl4[0], kl4[1], kl4[2], kl4[3], kb);
                #pragma unroll
                for (int hf = 0; hf < 2; hf++) {
                    const int nb = nbp * 2 + hf;
                    uint32_t bh2[2] = { kh4[hf*2], kh4[hf*2+1] };
                    uint32_t bl2[2] = { kl4[hf*2], kl4[hf*2+1] };
                    mma_bf16(sacc[nb], qh[ks], bh2);
                    mma_bf16(sacc[nb], qh[ks], bl2);
                    mma_bf16(sacc[nb], ql[ks], bh2);
                }
            }
        }

        // ---- causal mask (only tiles near diagonal) ----
        if (k0 + 63 > qrow) {
            #pragma unroll
            for (int nb = 0; nb < 8; nb++)
                #pragma unroll
                for (int c = 0; c < 4; c++) {
                    const int kg = k0 + nb * 8 + (lane & 3) * 2 + (c & 1);
                    const int qg = qrow + ((c >= 2) ? 8 : 0);
                    if (kg > qg) sacc[nb][c] = -1e30f;
                }
        }

        // ---- online softmax (per thread: 2 rows) ----
        #pragma unroll
        for (int r = 0; r < 2; r++) {
            float tm = -1e30f;
            #pragma unroll
            for (int nb = 0; nb < 8; nb++)
                tm = fmaxf(tm, fmaxf(sacc[nb][2*r], sacc[nb][2*r+1]));
            tm = fmaxf(tm, __shfl_xor_sync(0xffffffffu, tm, 1));
            tm = fmaxf(tm, __shfl_xor_sync(0xffffffffu, tm, 2));
            const float mn = fmaxf(mrun[r], tm);
            const float al = __expf(mrun[r] - mn);
            mrun[r] = mn;
            float rs = 0.0f;
            #pragma unroll
            for (int nb = 0; nb < 8; nb++) {
                float p0 = __expf(sacc[nb][2*r]   - mn);
                float p1 = __expf(sacc[nb][2*r+1] - mn);
                sacc[nb][2*r] = p0; sacc[nb][2*r+1] = p1;
                rs += p0 + p1;
            }
            rs += __shfl_xor_sync(0xffffffffu, rs, 1);
            rs += __shfl_xor_sync(0xffffffffu, rs, 2);
            lsum[r] = lsum[r] * al + rs;
            #pragma unroll
            for (int dn = 0; dn < 8; dn++) {
                oacc[dn][2*r] *= al; oacc[dn][2*r+1] *= al;
            }
        }

        // ---- O += P V  (P: C-frag -> A-frag in registers; 3-pass split) ----
        #pragma unroll
        for (int j = 0; j < 4; j++) {          // k-step over 16 keys
            uint32_t ah[4], al4[4];
            pack_hilo(sacc[2*j][0],   sacc[2*j][1],   ah[0], al4[0]);
            pack_hilo(sacc[2*j][2],   sacc[2*j][3],   ah[1], al4[1]);
            pack_hilo(sacc[2*j+1][0], sacc[2*j+1][1], ah[2], al4[2]);
            pack_hilo(sacc[2*j+1][2], sacc[2*j+1][3], ah[3], al4[3]);
            #pragma unroll
            for (int dnp = 0; dnp < 4; dnp++) {
                uint32_t vh4[4], vl4[4];
                uint32_t va = smem_u32(&s.VThi[(dnp * 16 + b_n) * ALD + j * 16 + b_k]);
                ldsm_x4(vh4[0], vh4[1], vh4[2], vh4[3], va);
                uint32_t vb = smem_u32(&s.VTlo[(dnp * 16 + b_n) * ALD + j * 16 + b_k]);
                ldsm_x4(vl4[0], vl4[1], vl4[2], vl4[3], vb);
                #pragma unroll
                for (int hf = 0; hf < 2; hf++) {
                    const int dn = dnp * 2 + hf;
                    uint32_t bh2[2] = { vh4[hf*2], vh4[hf*2+1] };
                    uint32_t bl2[2] = { vl4[hf*2], vl4[hf*2+1] };
                    mma_bf16(oacc[dn], ah, bh2);
                    mma_bf16(oacc[dn], ah, bl2);
                    mma_bf16(oacc[dn], al4, bh2);
                }
            }
        }
    }

    // ---- epilogue: normalize, split, write [B*T, C] ----
    const int b = bh >> 4, h = bh & 15;
    #pragma unroll
    for (int r = 0; r < 2; r++) {
        const float inv = 1.0f / lsum[r];
        const int row = q0 + w * 16 + (lane >> 2) + r * 8;
        const size_t off = (size_t)(b * TT + row) * CC + h * DD;
        #pragma unroll
        for (int dn = 0; dn < 8; dn++) {
            const int col = dn * 8 + (lane & 3) * 2;
            uint32_t vh, vl;
            pack_hilo(oacc[dn][2*r] * inv, oacc[dn][2*r+1] * inv, vh, vl);
            *(uint32_t*)(g_Ohi + off + col) = vh;
            *(uint32_t*)(g_Olo + off + col) = vl;
        }
    }
}

// ---------------------------------------------------------------------------
extern "C" void kernel_launch(void* const* d_in, const int* in_sizes, int n_in,
                              void* d_out, int out_size)
{
    const float* x     = (const float*)d_in[0];   // [4,2048,1024]
    const float* wqkv  = (const float*)d_in[1];   // [3072,1024]
    const float* wproj = (const float*)d_in[2];   // [1024,1024]
    float* out = (float*)d_out;                   // [4,2048,1024]

    cudaFuncSetAttribute((const void*)attn_mma_kernel,
                         cudaFuncAttributeMaxDynamicSharedMemorySize, ATTN_SMEM_BYTES);
    cudaFuncSetAttribute((const void*)mma_gemm_kernel<0>,
                         cudaFuncAttributeMaxDynamicSharedMemorySize, GEMM_SMEM_BYTES);
    cudaFuncSetAttribute((const void*)mma_gemm_kernel<1>,
                         cudaFuncAttributeMaxDynamicSharedMemorySize, GEMM_SMEM_BYTES);

    __nv_bfloat16 *xhi, *xlo, *wqhi, *wqlo, *wphi, *wplo, *ohi, *olo;
    cudaGetSymbolAddress((void**)&xhi,  g_Xhi);  cudaGetSymbolAddress((void**)&xlo,  g_Xlo);
    cudaGetSymbolAddress((void**)&wqhi, g_Wqhi); cudaGetSymbolAddress((void**)&wqlo, g_Wqlo);
    cudaGetSymbolAddress((void**)&wphi, g_Wphi); cudaGetSymbolAddress((void**)&wplo, g_Wplo);
    cudaGetSymbolAddress((void**)&ohi,  g_Ohi);  cudaGetSymbolAddress((void**)&olo,  g_Olo);

    split_kernel<<<(MM*CC/4 + 255)/256, 256>>>(x, xhi, xlo, MM*CC/4);
    split_kernel<<<(NQKV*CC/4 + 255)/256, 256>>>(wqkv, wqhi, wqlo, NQKV*CC/4);
    split_kernel<<<(CC*CC/4 + 255)/256, 256>>>(wproj, wphi, wplo, CC*CC/4);

    mma_gemm_kernel<0><<<dim3(NQKV/128, MM/128), 256, GEMM_SMEM_BYTES>>>(
        xhi, xlo, wqhi, wqlo, nullptr);

    attn_mma_kernel<<<dim3(TT/AQT, BB*HH), 256, ATTN_SMEM_BYTES>>>();

    mma_gemm_kernel<1><<<dim3(CC/128, MM/128), 256, GEMM_SMEM_BYTES>>>(
        ohi, olo, wphi, wplo, out);
}

// round 5
// speedup vs baseline: 2.4056x; 1.1198x over previous
#include <cuda_runtime.h>
#include <cuda_bf16.h>
#include <cstdint>
#include <math.h>

// Problem constants
#define BB 4
#define TT 2048
#define CC 1024
#define HH 16
#define DD 64
#define MM (BB*TT)          // 8192
#define NQKV (3*CC)         // 3072

// ---------------------------------------------------------------------------
// Scratch (__device__ globals; no allocation allowed)
// ---------------------------------------------------------------------------
__device__ __nv_bfloat16 g_Qhi[BB*HH*TT*DD], g_Qlo[BB*HH*TT*DD];
__device__ __nv_bfloat16 g_Khi[BB*HH*TT*DD], g_Klo[BB*HH*TT*DD];
__device__ __nv_bfloat16 g_Vhi[BB*HH*TT*DD], g_Vlo[BB*HH*TT*DD];

__device__ __nv_bfloat16 g_Xhi[MM*CC],  g_Xlo[MM*CC];
__device__ __nv_bfloat16 g_Wqhi[NQKV*CC], g_Wqlo[NQKV*CC];
__device__ __nv_bfloat16 g_Wphi[CC*CC], g_Wplo[CC*CC];
__device__ __nv_bfloat16 g_Ohi[MM*CC],  g_Olo[MM*CC];

// ---------------------------------------------------------------------------
// helpers
// ---------------------------------------------------------------------------
__device__ __forceinline__ uint32_t smem_u32(const void* p) {
    uint32_t a;
    asm("{ .reg .u64 t; cvta.to.shared.u64 t, %1; cvt.u32.u64 %0, t; }" : "=r"(a) : "l"(p));
    return a;
}
__device__ __forceinline__ void ldsm_x4(uint32_t& r0, uint32_t& r1, uint32_t& r2,
                                        uint32_t& r3, uint32_t addr) {
    asm volatile("ldmatrix.sync.aligned.m8n8.x4.shared.b16 {%0,%1,%2,%3}, [%4];"
                 : "=r"(r0), "=r"(r1), "=r"(r2), "=r"(r3) : "r"(addr));
}
__device__ __forceinline__ void ldsm_x4_t(uint32_t& r0, uint32_t& r1, uint32_t& r2,
                                          uint32_t& r3, uint32_t addr) {
    asm volatile("ldmatrix.sync.aligned.m8n8.x4.trans.shared.b16 {%0,%1,%2,%3}, [%4];"
                 : "=r"(r0), "=r"(r1), "=r"(r2), "=r"(r3) : "r"(addr));
}
__device__ __forceinline__ void mma_bf16(float* c, const uint32_t* a, const uint32_t* b) {
    asm volatile("mma.sync.aligned.m16n8k16.row.col.f32.bf16.bf16.f32 "
                 "{%0,%1,%2,%3}, {%4,%5,%6,%7}, {%8,%9}, {%0,%1,%2,%3};"
                 : "+f"(c[0]), "+f"(c[1]), "+f"(c[2]), "+f"(c[3])
                 : "r"(a[0]), "r"(a[1]), "r"(a[2]), "r"(a[3]), "r"(b[0]), "r"(b[1]));
}
__device__ __forceinline__ void cp16(uint32_t dst, const void* src) {
    asm volatile("cp.async.cg.shared.global [%0], [%1], 16;" :: "r"(dst), "l"(src));
}
#define CP_COMMIT() asm volatile("cp.async.commit_group;" ::: "memory")
#define CP_WAIT(N)  asm volatile("cp.async.wait_group %0;" :: "n"(N) : "memory")

__device__ __forceinline__ void split_f32(float x, __nv_bfloat16& hi, __nv_bfloat16& lo) {
    hi = __float2bfloat16(x);
    lo = __float2bfloat16(x - __bfloat162float(hi));
}
__device__ __forceinline__ uint32_t pack2(__nv_bfloat16 a, __nv_bfloat16 b) {
    __nv_bfloat162 t(a, b);
    return *reinterpret_cast<uint32_t*>(&t);
}
__device__ __forceinline__ void pack_hilo(float x, float y, uint32_t& hi, uint32_t& lo) {
    __nv_bfloat16 hx, lx, hy, ly;
    split_f32(x, hx, lx); split_f32(y, hy, ly);
    hi = pack2(hx, hy); lo = pack2(lx, ly);
}

// ---------------------------------------------------------------------------
// fp32 -> (hi,lo) bf16 split
// ---------------------------------------------------------------------------
__global__ __launch_bounds__(256) void split_kernel(const float* __restrict__ src,
                                                    __nv_bfloat16* __restrict__ hi,
                                                    __nv_bfloat16* __restrict__ lo, int n4)
{
    int i = blockIdx.x * blockDim.x + threadIdx.x;
    if (i >= n4) return;
    float4 v = ((const float4*)src)[i];
    __nv_bfloat16 h[4], l[4];
    split_f32(v.x, h[0], l[0]); split_f32(v.y, h[1], l[1]);
    split_f32(v.z, h[2], l[2]); split_f32(v.w, h[3], l[3]);
    ((__nv_bfloat162*)hi)[i*2+0] = __nv_bfloat162(h[0], h[1]);
    ((__nv_bfloat162*)hi)[i*2+1] = __nv_bfloat162(h[2], h[3]);
    ((__nv_bfloat162*)lo)[i*2+0] = __nv_bfloat162(l[0], l[1]);
    ((__nv_bfloat162*)lo)[i*2+1] = __nv_bfloat162(l[2], l[3]);
}

// ---------------------------------------------------------------------------
// HMMA split-bf16 GEMM with cp.async 4-stage pipeline.
// C[m,n] = sum_k A[m,k]*B[n,k]; 128x128 CTA tile, BK=32, 8 warps, 64x32 warp tile.
// MODE 0: split C -> g_{Q,K,V}{hi,lo} [B,H,T,D] (Q scaled 0.125). MODE 1: fp32 out.
// ---------------------------------------------------------------------------
#define BK 32
#define LDSR 40
#define TILE_ELE (128*LDSR)        // 5120
#define STAGE_ELE (4*TILE_ELE)     // 20480
#define NSTG 4
#define GEMM_SMEM_BYTES (NSTG*STAGE_ELE*2)   // 163840 B

template<int MODE>
__global__ __launch_bounds__(256, 1) void mma_gemm_kernel(
    const __nv_bfloat16* __restrict__ Ahi, const __nv_bfloat16* __restrict__ Alo,
    const __nv_bfloat16* __restrict__ Bhi, const __nv_bfloat16* __restrict__ Blo,
    float* __restrict__ out)
{
    extern __shared__ __nv_bfloat16 sm[];
    const uint32_t smb = smem_u32(sm);
    const int tid = threadIdx.x;
    const int lane = tid & 31, wid = tid >> 5;
    const int wm = (wid >> 2) * 64;
    const int wn = (wid & 3) * 32;
    const int n0 = blockIdx.x * 128;
    const int m0 = blockIdx.y * 128;

    const __nv_bfloat16* srcs[4] = {
        Ahi + (size_t)m0 * CC, Alo + (size_t)m0 * CC,
        Bhi + (size_t)n0 * CC, Blo + (size_t)n0 * CC };

    const int r0_ = tid >> 2, r1_ = 64 + (tid >> 2);
    const int c_ = (tid & 3) * 8;
    const int NCH = CC / BK;   // 32

    float acc[4][4][4];
    #pragma unroll
    for (int a = 0; a < 4; a++)
        #pragma unroll
        for (int b = 0; b < 4; b++)
            #pragma unroll
            for (int c = 0; c < 4; c++) acc[a][b][c] = 0.0f;

    const int a_m = ((lane >> 3) & 1) * 8 + (lane & 7);
    const int a_k = (lane >> 4) * 8;
    const int b_n = (lane >> 4) * 8 + (lane & 7);
    const int b_k = ((lane >> 3) & 1) * 8;

    // issue one chunk's 4 tiles into its stage
    auto issue_chunk = [&](int ch) {
        const uint32_t sbase = smb + (uint32_t)(ch & (NSTG - 1)) * (STAGE_ELE * 2);
        const int k0 = ch * BK;
        #pragma unroll
        for (int t = 0; t < 4; t++) {
            cp16(sbase + (uint32_t)(t * TILE_ELE + r0_ * LDSR + c_) * 2,
                 srcs[t] + (size_t)r0_ * CC + k0 + c_);
            cp16(sbase + (uint32_t)(t * TILE_ELE + r1_ * LDSR + c_) * 2,
                 srcs[t] + (size_t)r1_ * CC + k0 + c_);
        }
    };

    issue_chunk(0); CP_COMMIT();
    issue_chunk(1); CP_COMMIT();
    issue_chunk(2); CP_COMMIT();

    for (int ch = 0; ch < NCH; ch++) {
        CP_WAIT(2);
        __syncthreads();
        if (ch + 3 < NCH) issue_chunk(ch + 3);
        CP_COMMIT();

        const __nv_bfloat16* buf = sm + (ch & (NSTG - 1)) * STAGE_ELE;

        #pragma unroll
        for (int kk = 0; kk < BK; kk += 16) {
            uint32_t aH[4][4], aL[4][4], bH[2][4], bL[2][4];
            #pragma unroll
            for (int mi = 0; mi < 4; mi++) {
                const int m = wm + mi * 16 + a_m;
                uint32_t ad = smem_u32(buf + m * LDSR + kk + a_k);
                ldsm_x4(aH[mi][0], aH[mi][1], aH[mi][2], aH[mi][3], ad);
                ldsm_x4(aL[mi][0], aL[mi][1], aL[mi][2], aL[mi][3], ad + TILE_ELE * 2);
            }
            #pragma unroll
            for (int ni = 0; ni < 2; ni++) {
                const int n = wn + ni * 16 + b_n;
                uint32_t bd = smem_u32(buf + 2 * TILE_ELE + n * LDSR + kk + b_k);
                ldsm_x4(bH[ni][0], bH[ni][1], bH[ni][2], bH[ni][3], bd);
                ldsm_x4(bL[ni][0], bL[ni][1], bL[ni][2], bL[ni][3], bd + TILE_ELE * 2);
            }
            #pragma unroll
            for (int mi = 0; mi < 4; mi++)
                #pragma unroll
                for (int nj = 0; nj < 4; nj++) {
                    uint32_t bh[2] = { bH[nj >> 1][(nj & 1) * 2], bH[nj >> 1][(nj & 1) * 2 + 1] };
                    uint32_t bl[2] = { bL[nj >> 1][(nj & 1) * 2], bL[nj >> 1][(nj & 1) * 2 + 1] };
                    mma_bf16(acc[mi][nj], aH[mi], bh);
                    mma_bf16(acc[mi][nj], aH[mi], bl);
                    mma_bf16(acc[mi][nj], aL[mi], bh);
                }
        }
    }

    // epilogue
    if (MODE == 0) {
        const int which = n0 >> 10;
        __nv_bfloat16* dhi = (which == 0) ? g_Qhi : ((which == 1) ? g_Khi : g_Vhi);
        __nv_bfloat16* dlo = (which == 0) ? g_Qlo : ((which == 1) ? g_Klo : g_Vlo);
        const float scl = (which == 0) ? 0.125f : 1.0f;
        #pragma unroll
        for (int mi = 0; mi < 4; mi++)
            #pragma unroll
            for (int nj = 0; nj < 4; nj++) {
                const int row0 = m0 + wm + mi * 16 + (lane >> 2);
                const int col  = n0 + wn + nj * 8 + (lane & 3) * 2;
                const int o = col & 1023, hd = o >> 6, d = o & 63;
                #pragma unroll
                for (int h = 0; h < 2; h++) {
                    const int row = row0 + h * 8;
                    const int b = row >> 11, t = row & 2047;
                    uint32_t vh, vl;
                    pack_hilo(acc[mi][nj][h*2] * scl, acc[mi][nj][h*2+1] * scl, vh, vl);
                    size_t off = ((size_t)(b * HH + hd) * TT + t) * DD + d;
                    *(uint32_t*)(dhi + off) = vh;
                    *(uint32_t*)(dlo + off) = vl;
                }
            }
    } else {
        #pragma unroll
        for (int mi = 0; mi < 4; mi++)
            #pragma unroll
            for (int nj = 0; nj < 4; nj++) {
                const int row0 = m0 + wm + mi * 16 + (lane >> 2);
                const int col  = n0 + wn + nj * 8 + (lane & 3) * 2;
                #pragma unroll
                for (int h = 0; h < 2; h++) {
                    const int row = row0 + h * 8;
                    float2 v = make_float2(acc[mi][nj][h*2], acc[mi][nj][h*2+1]);
                    *(float2*)(out + (size_t)row * CC + col) = v;
                }
            }
    }
}

// ---------------------------------------------------------------------------
// Tensor-core flash attention (causal), cp.async 3-stage K/V pipeline,
// ldmatrix.trans for V (no smem transpose). 128 q/CTA, KTILE=64, 8 warps.
// ---------------------------------------------------------------------------
#define AQT 128
#define AKT 64
#define ALD 72

struct AttnSmem {
    __nv_bfloat16 Q[2][AQT*ALD];          // hi, lo
    __nv_bfloat16 KV[3][4][AKT*ALD];      // stage, {Khi,Klo,Vhi,Vlo}
};
#define ATTN_SMEM_BYTES ((int)sizeof(AttnSmem))   // 147456

__global__ __launch_bounds__(256, 1) void attn_mma_kernel()
{
    extern __shared__ char smraw[];
    AttnSmem& s = *(AttnSmem*)smraw;

    const int tid = threadIdx.x, lane = tid & 31, w = tid >> 5;
    const int bh = blockIdx.y;
    const int qi = gridDim.x - 1 - blockIdx.x;
    const int q0 = qi * AQT;
    const size_t base = (size_t)bh * TT * DD;
    const __nv_bfloat16* kvsrc[4] = { g_Khi + base, g_Klo + base, g_Vhi + base, g_Vlo + base };
    const __nv_bfloat16 *Qh = g_Qhi + base, *Ql = g_Qlo + base;

    const int nk = 2 * qi + 2;

    // per-thread K/V load slot: idx = l*256+tid -> row=idx>>3, chunk=(idx&7)*8
    const int kr0 = tid >> 3, kr1 = 32 + (tid >> 3);
    const int kc = (tid & 7) * 8;

    auto issue_kv = [&](int kt) {
        const int st = kt % 3;
        const int k0 = kt * AKT;
        #pragma unroll
        for (int t = 0; t < 4; t++) {
            cp16(smem_u32(&s.KV[st][t][kr0 * ALD + kc]),
                 kvsrc[t] + (size_t)(k0 + kr0) * DD + kc);
            cp16(smem_u32(&s.KV[st][t][kr1 * ALD + kc]),
                 kvsrc[t] + (size_t)(k0 + kr1) * DD + kc);
        }
    };

    issue_kv(0); CP_COMMIT();
    issue_kv(1); CP_COMMIT();

    // Q tile -> smem (plain loads)
    #pragma unroll
    for (int l = 0; l < 4; l++) {
        int idx = l * 256 + tid;
        int r = idx >> 3, d0 = (idx & 7) * 8;
        *(uint4*)&s.Q[0][r * ALD + d0] = *(const uint4*)(Qh + (size_t)(q0 + r) * DD + d0);
        *(uint4*)&s.Q[1][r * ALD + d0] = *(const uint4*)(Ql + (size_t)(q0 + r) * DD + d0);
    }
    __syncthreads();

    const int a_m = ((lane >> 3) & 1) * 8 + (lane & 7);
    const int a_k = (lane >> 4) * 8;
    const int b_n = (lane >> 4) * 8 + (lane & 7);
    const int b_k = ((lane >> 3) & 1) * 8;
    // trans-V lane addressing: stored rows = key, cols = d
    const int t_r = ((lane >> 3) & 1) * 8 + (lane & 7);
    const int t_c = (lane >> 4) * 8;

    // persistent Q fragments
    uint32_t qh[4][4], ql[4][4];
    #pragma unroll
    for (int ks = 0; ks < 4; ks++) {
        uint32_t qa = smem_u32(&s.Q[0][(w * 16 + a_m) * ALD + ks * 16 + a_k]);
        ldsm_x4(qh[ks][0], qh[ks][1], qh[ks][2], qh[ks][3], qa);
        uint32_t qb = smem_u32(&s.Q[1][(w * 16 + a_m) * ALD + ks * 16 + a_k]);
        ldsm_x4(ql[ks][0], ql[ks][1], ql[ks][2], ql[ks][3], qb);
    }

    float oacc[8][4];
    #pragma unroll
    for (int i = 0; i < 8; i++)
        #pragma unroll
        for (int j = 0; j < 4; j++) oacc[i][j] = 0.0f;
    float mrun[2] = { -1e30f, -1e30f }, lsum[2] = { 0.0f, 0.0f };

    const int qrow = q0 + w * 16 + (lane >> 2);

    for (int kt = 0; kt < nk; kt++) {
        const int k0 = kt * AKT;
        CP_WAIT(1);
        __syncthreads();
        if (kt + 2 < nk) issue_kv(kt + 2);
        CP_COMMIT();

        const int st = kt % 3;
        const __nv_bfloat16* Khs = s.KV[st][0];
        const __nv_bfloat16* Kls = s.KV[st][1];
        const __nv_bfloat16* Vhs = s.KV[st][2];
        const __nv_bfloat16* Vls = s.KV[st][3];

        // ---- S = Q K^T (3-pass) ----
        float sacc[8][4];
        #pragma unroll
        for (int i = 0; i < 8; i++)
            #pragma unroll
            for (int j = 0; j < 4; j++) sacc[i][j] = 0.0f;

        #pragma unroll
        for (int nbp = 0; nbp < 4; nbp++) {
            #pragma unroll
            for (int ks = 0; ks < 4; ks++) {
                uint32_t kh4[4], kl4[4];
                uint32_t ka = smem_u32(Khs + (nbp * 16 + b_n) * ALD + ks * 16 + b_k);
                ldsm_x4(kh4[0], kh4[1], kh4[2], kh4[3], ka);
                uint32_t kb = smem_u32(Kls + (nbp * 16 + b_n) * ALD + ks * 16 + b_k);
                ldsm_x4(kl4[0], kl4[1], kl4[2], kl4[3], kb);
                #pragma unroll
                for (int hf = 0; hf < 2; hf++) {
                    const int nb = nbp * 2 + hf;
                    uint32_t bh2[2] = { kh4[hf*2], kh4[hf*2+1] };
                    uint32_t bl2[2] = { kl4[hf*2], kl4[hf*2+1] };
                    mma_bf16(sacc[nb], qh[ks], bh2);
                    mma_bf16(sacc[nb], qh[ks], bl2);
                    mma_bf16(sacc[nb], ql[ks], bh2);
                }
            }
        }

        // ---- causal mask ----
        if (k0 + 63 > qrow) {
            #pragma unroll
            for (int nb = 0; nb < 8; nb++)
                #pragma unroll
                for (int c = 0; c < 4; c++) {
                    const int kg = k0 + nb * 8 + (lane & 3) * 2 + (c & 1);
                    const int qg = qrow + ((c >= 2) ? 8 : 0);
                    if (kg > qg) sacc[nb][c] = -1e30f;
                }
        }

        // ---- online softmax ----
        #pragma unroll
        for (int r = 0; r < 2; r++) {
            float tm = -1e30f;
            #pragma unroll
            for (int nb = 0; nb < 8; nb++)
                tm = fmaxf(tm, fmaxf(sacc[nb][2*r], sacc[nb][2*r+1]));
            tm = fmaxf(tm, __shfl_xor_sync(0xffffffffu, tm, 1));
            tm = fmaxf(tm, __shfl_xor_sync(0xffffffffu, tm, 2));
            const float mn = fmaxf(mrun[r], tm);
            const float al = __expf(mrun[r] - mn);
            mrun[r] = mn;
            float rs = 0.0f;
            #pragma unroll
            for (int nb = 0; nb < 8; nb++) {
                float p0 = __expf(sacc[nb][2*r]   - mn);
                float p1 = __expf(sacc[nb][2*r+1] - mn);
                sacc[nb][2*r] = p0; sacc[nb][2*r+1] = p1;
                rs += p0 + p1;
            }
            rs += __shfl_xor_sync(0xffffffffu, rs, 1);
            rs += __shfl_xor_sync(0xffffffffu, rs, 2);
            lsum[r] = lsum[r] * al + rs;
            #pragma unroll
            for (int dn = 0; dn < 8; dn++) {
                oacc[dn][2*r] *= al; oacc[dn][2*r+1] *= al;
            }
        }

        // ---- O += P V (trans-ldmatrix V; 3-pass) ----
        #pragma unroll
        for (int j = 0; j < 4; j++) {
            uint32_t ah[4], al4[4];
            pack_hilo(sacc[2*j][0],   sacc[2*j][1],   ah[0], al4[0]);
            pack_hilo(sacc[2*j][2],   sacc[2*j][3],   ah[1], al4[1]);
            pack_hilo(sacc[2*j+1][0], sacc[2*j+1][1], ah[2], al4[2]);
            pack_hilo(sacc[2*j+1][2], sacc[2*j+1][3], ah[3], al4[3]);
            #pragma unroll
            for (int dnp = 0; dnp < 4; dnp++) {
                uint32_t vh4[4], vl4[4];
                uint32_t va = smem_u32(Vhs + (j * 16 + t_r) * ALD + dnp * 16 + t_c);
                ldsm_x4_t(vh4[0], vh4[1], vh4[2], vh4[3], va);
                uint32_t vb = smem_u32(Vls + (j * 16 + t_r) * ALD + dnp * 16 + t_c);
                ldsm_x4_t(vl4[0], vl4[1], vl4[2], vl4[3], vb);
                #pragma unroll
                for (int hf = 0; hf < 2; hf++) {
                    const int dn = dnp * 2 + hf;
                    uint32_t bh2[2] = { vh4[hf*2], vh4[hf*2+1] };
                    uint32_t bl2[2] = { vl4[hf*2], vl4[hf*2+1] };
                    mma_bf16(oacc[dn], ah, bh2);
                    mma_bf16(oacc[dn], ah, bl2);
                    mma_bf16(oacc[dn], al4, bh2);
                }
            }
        }
    }

    // ---- epilogue ----
    const int b = bh >> 4, h = bh & 15;
    #pragma unroll
    for (int r = 0; r < 2; r++) {
        const float inv = 1.0f / lsum[r];
        const int row = q0 + w * 16 + (lane >> 2) + r * 8;
        const size_t off = (size_t)(b * TT + row) * CC + h * DD;
        #pragma unroll
        for (int dn = 0; dn < 8; dn++) {
            const int col = dn * 8 + (lane & 3) * 2;
            uint32_t vh, vl;
            pack_hilo(oacc[dn][2*r] * inv, oacc[dn][2*r+1] * inv, vh, vl);
            *(uint32_t*)(g_Ohi + off + col) = vh;
            *(uint32_t*)(g_Olo + off + col) = vl;
        }
    }
}

// ---------------------------------------------------------------------------
extern "C" void kernel_launch(void* const* d_in, const int* in_sizes, int n_in,
                              void* d_out, int out_size)
{
    const float* x     = (const float*)d_in[0];
    const float* wqkv  = (const float*)d_in[1];
    const float* wproj = (const float*)d_in[2];
    float* out = (float*)d_out;

    cudaFuncSetAttribute((const void*)attn_mma_kernel,
                         cudaFuncAttributeMaxDynamicSharedMemorySize, ATTN_SMEM_BYTES);
    cudaFuncSetAttribute((const void*)mma_gemm_kernel<0>,
                         cudaFuncAttributeMaxDynamicSharedMemorySize, GEMM_SMEM_BYTES);
    cudaFuncSetAttribute((const void*)mma_gemm_kernel<1>,
                         cudaFuncAttributeMaxDynamicSharedMemorySize, GEMM_SMEM_BYTES);

    __nv_bfloat16 *xhi, *xlo, *wqhi, *wqlo, *wphi, *wplo, *ohi, *olo;
    cudaGetSymbolAddress((void**)&xhi,  g_Xhi);  cudaGetSymbolAddress((void**)&xlo,  g_Xlo);
    cudaGetSymbolAddress((void**)&wqhi, g_Wqhi); cudaGetSymbolAddress((void**)&wqlo, g_Wqlo);
    cudaGetSymbolAddress((void**)&wphi, g_Wphi); cudaGetSymbolAddress((void**)&wplo, g_Wplo);
    cudaGetSymbolAddress((void**)&ohi,  g_Ohi);  cudaGetSymbolAddress((void**)&olo,  g_Olo);

    split_kernel<<<(MM*CC/4 + 255)/256, 256>>>(x, xhi, xlo, MM*CC/4);
    split_kernel<<<(NQKV*CC/4 + 255)/256, 256>>>(wqkv, wqhi, wqlo, NQKV*CC/4);
    split_kernel<<<(CC*CC/4 + 255)/256, 256>>>(wproj, wphi, wplo, CC*CC/4);

    mma_gemm_kernel<0><<<dim3(NQKV/128, MM/128), 256, GEMM_SMEM_BYTES>>>(
        xhi, xlo, wqhi, wqlo, nullptr);

    attn_mma_kernel<<<dim3(TT/AQT, BB*HH), 256, ATTN_SMEM_BYTES>>>();

    mma_gemm_kernel<1><<<dim3(CC/128, MM/128), 256, GEMM_SMEM_BYTES>>>(
        ohi, olo, wphi, wplo, out);
}

// round 6
// speedup vs baseline: 2.4243x; 1.0078x over previous
#include <cuda_runtime.h>
#include <cuda_bf16.h>
#include <cstdint>
#include <math.h>

// Problem constants
#define BB 4
#define TT 2048
#define CC 1024
#define HH 16
#define DD 64
#define MM (BB*TT)          // 8192
#define NQKV (3*CC)         // 3072

// ---------------------------------------------------------------------------
// Scratch (__device__ globals; no allocation allowed)
// ---------------------------------------------------------------------------
__device__ __nv_bfloat16 g_Qhi[BB*HH*TT*DD], g_Qlo[BB*HH*TT*DD];
__device__ __nv_bfloat16 g_Khi[BB*HH*TT*DD], g_Klo[BB*HH*TT*DD];
__device__ __nv_bfloat16 g_Vhi[BB*HH*TT*DD], g_Vlo[BB*HH*TT*DD];

__device__ __nv_bfloat16 g_Xhi[MM*CC],  g_Xlo[MM*CC];
__device__ __nv_bfloat16 g_Wqhi[NQKV*CC], g_Wqlo[NQKV*CC];
__device__ __nv_bfloat16 g_Wphi[CC*CC], g_Wplo[CC*CC];
__device__ __nv_bfloat16 g_Ohi[MM*CC],  g_Olo[MM*CC];

// ---------------------------------------------------------------------------
// helpers
// ---------------------------------------------------------------------------
__device__ __forceinline__ uint32_t smem_u32(const void* p) {
    uint32_t a;
    asm("{ .reg .u64 t; cvta.to.shared.u64 t, %1; cvt.u32.u64 %0, t; }" : "=r"(a) : "l"(p));
    return a;
}
__device__ __forceinline__ void ldsm_x4(uint32_t& r0, uint32_t& r1, uint32_t& r2,
                                        uint32_t& r3, uint32_t addr) {
    asm volatile("ldmatrix.sync.aligned.m8n8.x4.shared.b16 {%0,%1,%2,%3}, [%4];"
                 : "=r"(r0), "=r"(r1), "=r"(r2), "=r"(r3) : "r"(addr));
}
__device__ __forceinline__ void ldsm_x4_t(uint32_t& r0, uint32_t& r1, uint32_t& r2,
                                          uint32_t& r3, uint32_t addr) {
    asm volatile("ldmatrix.sync.aligned.m8n8.x4.trans.shared.b16 {%0,%1,%2,%3}, [%4];"
                 : "=r"(r0), "=r"(r1), "=r"(r2), "=r"(r3) : "r"(addr));
}
__device__ __forceinline__ void mma_bf16(float* c, const uint32_t* a, const uint32_t* b) {
    asm volatile("mma.sync.aligned.m16n8k16.row.col.f32.bf16.bf16.f32 "
                 "{%0,%1,%2,%3}, {%4,%5,%6,%7}, {%8,%9}, {%0,%1,%2,%3};"
                 : "+f"(c[0]), "+f"(c[1]), "+f"(c[2]), "+f"(c[3])
                 : "r"(a[0]), "r"(a[1]), "r"(a[2]), "r"(a[3]), "r"(b[0]), "r"(b[1]));
}
__device__ __forceinline__ void cp16(uint32_t dst, const void* src) {
    asm volatile("cp.async.cg.shared.global [%0], [%1], 16;" :: "r"(dst), "l"(src));
}
#define CP_COMMIT() asm volatile("cp.async.commit_group;" ::: "memory")
#define CP_WAIT(N)  asm volatile("cp.async.wait_group %0;" :: "n"(N) : "memory")

__device__ __forceinline__ void split_f32(float x, __nv_bfloat16& hi, __nv_bfloat16& lo) {
    hi = __float2bfloat16(x);
    lo = __float2bfloat16(x - __bfloat162float(hi));
}
__device__ __forceinline__ uint32_t pack2(__nv_bfloat16 a, __nv_bfloat16 b) {
    __nv_bfloat162 t(a, b);
    return *reinterpret_cast<uint32_t*>(&t);
}
__device__ __forceinline__ void pack_hilo(float x, float y, uint32_t& hi, uint32_t& lo) {
    __nv_bfloat16 hx, lx, hy, ly;
    split_f32(x, hx, lx); split_f32(y, hy, ly);
    hi = pack2(hx, hy); lo = pack2(lx, ly);
}

// ---------------------------------------------------------------------------
// fp32 -> (hi,lo) bf16 split
// ---------------------------------------------------------------------------
__global__ __launch_bounds__(256) void split_kernel(const float* __restrict__ src,
                                                    __nv_bfloat16* __restrict__ hi,
                                                    __nv_bfloat16* __restrict__ lo, int n4)
{
    int i = blockIdx.x * blockDim.x + threadIdx.x;
    if (i >= n4) return;
    float4 v = ((const float4*)src)[i];
    __nv_bfloat16 h[4], l[4];
    split_f32(v.x, h[0], l[0]); split_f32(v.y, h[1], l[1]);
    split_f32(v.z, h[2], l[2]); split_f32(v.w, h[3], l[3]);
    ((__nv_bfloat162*)hi)[i*2+0] = __nv_bfloat162(h[0], h[1]);
    ((__nv_bfloat162*)hi)[i*2+1] = __nv_bfloat162(h[2], h[3]);
    ((__nv_bfloat162*)lo)[i*2+0] = __nv_bfloat162(l[0], l[1]);
    ((__nv_bfloat162*)lo)[i*2+1] = __nv_bfloat162(l[2], l[3]);
}

// ---------------------------------------------------------------------------
// HMMA split-bf16 GEMM, 512 threads / 16 warps, warp tile 32x32.
// C[m,n] = sum_k A[m,k]*B[n,k]; 128x128 CTA tile, BK=32, 3-stage cp.async.
// MODE 0: split C -> g_{Q,K,V}{hi,lo} [B,H,T,D] (Q scaled 0.125). MODE 1: fp32 out.
// ---------------------------------------------------------------------------
#define BK 32
#define LDSR 40
#define TILE_ELE (128*LDSR)        // 5120
#define STAGE_ELE (4*TILE_ELE)     // 20480
#define NSTG 3
#define GEMM_SMEM_BYTES (NSTG*STAGE_ELE*2)   // 122880 B
#define GEMM_THREADS 512

template<int MODE>
__global__ __launch_bounds__(GEMM_THREADS, 1) void mma_gemm_kernel(
    const __nv_bfloat16* __restrict__ Ahi, const __nv_bfloat16* __restrict__ Alo,
    const __nv_bfloat16* __restrict__ Bhi, const __nv_bfloat16* __restrict__ Blo,
    float* __restrict__ out)
{
    extern __shared__ __nv_bfloat16 sm[];
    const uint32_t smb = smem_u32(sm);
    const int tid = threadIdx.x;
    const int lane = tid & 31, wid = tid >> 5;     // wid 0..15
    const int wm = (wid >> 2) * 32;                // 0,32,64,96
    const int wn = (wid & 3) * 32;                 // 0,32,64,96
    const int n0 = blockIdx.x * 128;
    const int m0 = blockIdx.y * 128;

    const __nv_bfloat16* srcs[4] = {
        Ahi + (size_t)m0 * CC, Alo + (size_t)m0 * CC,
        Bhi + (size_t)n0 * CC, Blo + (size_t)n0 * CC };

    const int NCH = CC / BK;   // 32

    float acc[2][4][4];
    #pragma unroll
    for (int a = 0; a < 2; a++)
        #pragma unroll
        for (int b = 0; b < 4; b++)
            #pragma unroll
            for (int c = 0; c < 4; c++) acc[a][b][c] = 0.0f;

    const int a_m = ((lane >> 3) & 1) * 8 + (lane & 7);
    const int a_k = (lane >> 4) * 8;
    const int b_n = (lane >> 4) * 8 + (lane & 7);
    const int b_k = ((lane >> 3) & 1) * 8;

    // issue one chunk (4 tiles of 128x32 bf16) into its stage; 4 cp16/thread
    auto issue_chunk = [&](int ch) {
        const uint32_t sbase = smb + (uint32_t)(ch % NSTG) * (STAGE_ELE * 2);
        const int k0 = ch * BK;
        #pragma unroll
        for (int l = 0; l < 4; l++) {
            const int o = l * GEMM_THREADS + tid;     // 0..2047
            const int tile = o >> 9;
            const int r = (o >> 2) & 127;
            const int c = (o & 3) * 8;
            cp16(sbase + (uint32_t)(tile * TILE_ELE + r * LDSR + c) * 2,
                 srcs[tile] + (size_t)r * CC + k0 + c);
        }
    };

    issue_chunk(0); CP_COMMIT();
    issue_chunk(1); CP_COMMIT();

    for (int ch = 0; ch < NCH; ch++) {
        CP_WAIT(1);
        __syncthreads();
        if (ch + 2 < NCH) issue_chunk(ch + 2);
        CP_COMMIT();

        const __nv_bfloat16* buf = sm + (ch % NSTG) * STAGE_ELE;

        #pragma unroll
        for (int kk = 0; kk < BK; kk += 16) {
            uint32_t aH[2][4], aL[2][4], bH[2][4], bL[2][4];
            #pragma unroll
            for (int mi = 0; mi < 2; mi++) {
                const int m = wm + mi * 16 + a_m;
                uint32_t ad = smem_u32(buf + m * LDSR + kk + a_k);
                ldsm_x4(aH[mi][0], aH[mi][1], aH[mi][2], aH[mi][3], ad);
                ldsm_x4(aL[mi][0], aL[mi][1], aL[mi][2], aL[mi][3], ad + TILE_ELE * 2);
            }
            #pragma unroll
            for (int ni = 0; ni < 2; ni++) {
                const int n = wn + ni * 16 + b_n;
                uint32_t bd = smem_u32(buf + 2 * TILE_ELE + n * LDSR + kk + b_k);
                ldsm_x4(bH[ni][0], bH[ni][1], bH[ni][2], bH[ni][3], bd);
                ldsm_x4(bL[ni][0], bL[ni][1], bL[ni][2], bL[ni][3], bd + TILE_ELE * 2);
            }
            #pragma unroll
            for (int mi = 0; mi < 2; mi++)
                #pragma unroll
                for (int nj = 0; nj < 4; nj++) {
                    uint32_t bh[2] = { bH[nj >> 1][(nj & 1) * 2], bH[nj >> 1][(nj & 1) * 2 + 1] };
                    uint32_t bl[2] = { bL[nj >> 1][(nj & 1) * 2], bL[nj >> 1][(nj & 1) * 2 + 1] };
                    mma_bf16(acc[mi][nj], aH[mi], bh);
                    mma_bf16(acc[mi][nj], aH[mi], bl);
                    mma_bf16(acc[mi][nj], aL[mi], bh);
                }
        }
    }

    // epilogue
    if (MODE == 0) {
        const int which = n0 >> 10;
        __nv_bfloat16* dhi = (which == 0) ? g_Qhi : ((which == 1) ? g_Khi : g_Vhi);
        __nv_bfloat16* dlo = (which == 0) ? g_Qlo : ((which == 1) ? g_Klo : g_Vlo);
        const float scl = (which == 0) ? 0.125f : 1.0f;
        #pragma unroll
        for (int mi = 0; mi < 2; mi++)
            #pragma unroll
            for (int nj = 0; nj < 4; nj++) {
                const int row0 = m0 + wm + mi * 16 + (lane >> 2);
                const int col  = n0 + wn + nj * 8 + (lane & 3) * 2;
                const int o = col & 1023, hd = o >> 6, d = o & 63;
                #pragma unroll
                for (int h = 0; h < 2; h++) {
                    const int row = row0 + h * 8;
                    const int b = row >> 11, t = row & 2047;
                    uint32_t vh, vl;
                    pack_hilo(acc[mi][nj][h*2] * scl, acc[mi][nj][h*2+1] * scl, vh, vl);
                    size_t off = ((size_t)(b * HH + hd) * TT + t) * DD + d;
                    *(uint32_t*)(dhi + off) = vh;
                    *(uint32_t*)(dlo + off) = vl;
                }
            }
    } else {
        #pragma unroll
        for (int mi = 0; mi < 2; mi++)
            #pragma unroll
            for (int nj = 0; nj < 4; nj++) {
                const int row0 = m0 + wm + mi * 16 + (lane >> 2);
                const int col  = n0 + wn + nj * 8 + (lane & 3) * 2;
                #pragma unroll
                for (int h = 0; h < 2; h++) {
                    const int row = row0 + h * 8;
                    float2 v = make_float2(acc[mi][nj][h*2], acc[mi][nj][h*2+1]);
                    *(float2*)(out + (size_t)row * CC + col) = v;
                }
            }
    }
}

// ---------------------------------------------------------------------------
// Tensor-core flash attention (causal), cp.async 3-stage K/V pipeline,
// ldmatrix.trans for V. 128 q/CTA, KTILE=64, 8 warps. (unchanged from R5)
// ---------------------------------------------------------------------------
#define AQT 128
#define AKT 64
#define ALD 72

struct AttnSmem {
    __nv_bfloat16 Q[2][AQT*ALD];          // hi, lo
    __nv_bfloat16 KV[3][4][AKT*ALD];      // stage, {Khi,Klo,Vhi,Vlo}
};
#define ATTN_SMEM_BYTES ((int)sizeof(AttnSmem))   // 147456

__global__ __launch_bounds__(256, 1) void attn_mma_kernel()
{
    extern __shared__ char smraw[];
    AttnSmem& s = *(AttnSmem*)smraw;

    const int tid = threadIdx.x, lane = tid & 31, w = tid >> 5;
    const int bh = blockIdx.y;
    const int qi = gridDim.x - 1 - blockIdx.x;
    const int q0 = qi * AQT;
    const size_t base = (size_t)bh * TT * DD;
    const __nv_bfloat16* kvsrc[4] = { g_Khi + base, g_Klo + base, g_Vhi + base, g_Vlo + base };
    const __nv_bfloat16 *Qh = g_Qhi + base, *Ql = g_Qlo + base;

    const int nk = 2 * qi + 2;

    const int kr0 = tid >> 3, kr1 = 32 + (tid >> 3);
    const int kc = (tid & 7) * 8;

    auto issue_kv = [&](int kt) {
        const int st = kt % 3;
        const int k0 = kt * AKT;
        #pragma unroll
        for (int t = 0; t < 4; t++) {
            cp16(smem_u32(&s.KV[st][t][kr0 * ALD + kc]),
                 kvsrc[t] + (size_t)(k0 + kr0) * DD + kc);
            cp16(smem_u32(&s.KV[st][t][kr1 * ALD + kc]),
                 kvsrc[t] + (size_t)(k0 + kr1) * DD + kc);
        }
    };

    issue_kv(0); CP_COMMIT();
    issue_kv(1); CP_COMMIT();

    #pragma unroll
    for (int l = 0; l < 4; l++) {
        int idx = l * 256 + tid;
        int r = idx >> 3, d0 = (idx & 7) * 8;
        *(uint4*)&s.Q[0][r * ALD + d0] = *(const uint4*)(Qh + (size_t)(q0 + r) * DD + d0);
        *(uint4*)&s.Q[1][r * ALD + d0] = *(const uint4*)(Ql + (size_t)(q0 + r) * DD + d0);
    }
    __syncthreads();

    const int a_m = ((lane >> 3) & 1) * 8 + (lane & 7);
    const int a_k = (lane >> 4) * 8;
    const int b_n = (lane >> 4) * 8 + (lane & 7);
    const int b_k = ((lane >> 3) & 1) * 8;
    const int t_r = ((lane >> 3) & 1) * 8 + (lane & 7);
    const int t_c = (lane >> 4) * 8;

    uint32_t qh[4][4], ql[4][4];
    #pragma unroll
    for (int ks = 0; ks < 4; ks++) {
        uint32_t qa = smem_u32(&s.Q[0][(w * 16 + a_m) * ALD + ks * 16 + a_k]);
        ldsm_x4(qh[ks][0], qh[ks][1], qh[ks][2], qh[ks][3], qa);
        uint32_t qb = smem_u32(&s.Q[1][(w * 16 + a_m) * ALD + ks * 16 + a_k]);
        ldsm_x4(ql[ks][0], ql[ks][1], ql[ks][2], ql[ks][3], qb);
    }

    float oacc[8][4];
    #pragma unroll
    for (int i = 0; i < 8; i++)
        #pragma unroll
        for (int j = 0; j < 4; j++) oacc[i][j] = 0.0f;
    float mrun[2] = { -1e30f, -1e30f }, lsum[2] = { 0.0f, 0.0f };

    const int qrow = q0 + w * 16 + (lane >> 2);

    for (int kt = 0; kt < nk; kt++) {
        const int k0 = kt * AKT;
        CP_WAIT(1);
        __syncthreads();
        if (kt + 2 < nk) issue_kv(kt + 2);
        CP_COMMIT();

        const int st = kt % 3;
        const __nv_bfloat16* Khs = s.KV[st][0];
        const __nv_bfloat16* Kls = s.KV[st][1];
        const __nv_bfloat16* Vhs = s.KV[st][2];
        const __nv_bfloat16* Vls = s.KV[st][3];

        float sacc[8][4];
        #pragma unroll
        for (int i = 0; i < 8; i++)
            #pragma unroll
            for (int j = 0; j < 4; j++) sacc[i][j] = 0.0f;

        #pragma unroll
        for (int nbp = 0; nbp < 4; nbp++) {
            #pragma unroll
            for (int ks = 0; ks < 4; ks++) {
                uint32_t kh4[4], kl4[4];
                uint32_t ka = smem_u32(Khs + (nbp * 16 + b_n) * ALD + ks * 16 + b_k);
                ldsm_x4(kh4[0], kh4[1], kh4[2], kh4[3], ka);
                uint32_t kb = smem_u32(Kls + (nbp * 16 + b_n) * ALD + ks * 16 + b_k);
                ldsm_x4(kl4[0], kl4[1], kl4[2], kl4[3], kb);
                #pragma unroll
                for (int hf = 0; hf < 2; hf++) {
                    const int nb = nbp * 2 + hf;
                    uint32_t bh2[2] = { kh4[hf*2], kh4[hf*2+1] };
                    uint32_t bl2[2] = { kl4[hf*2], kl4[hf*2+1] };
                    mma_bf16(sacc[nb], qh[ks], bh2);
                    mma_bf16(sacc[nb], qh[ks], bl2);
                    mma_bf16(sacc[nb], ql[ks], bh2);
                }
            }
        }

        if (k0 + 63 > qrow) {
            #pragma unroll
            for (int nb = 0; nb < 8; nb++)
                #pragma unroll
                for (int c = 0; c < 4; c++) {
                    const int kg = k0 + nb * 8 + (lane & 3) * 2 + (c & 1);
                    const int qg = qrow + ((c >= 2) ? 8 : 0);
                    if (kg > qg) sacc[nb][c] = -1e30f;
                }
        }

        #pragma unroll
        for (int r = 0; r < 2; r++) {
            float tm = -1e30f;
            #pragma unroll
            for (int nb = 0; nb < 8; nb++)
                tm = fmaxf(tm, fmaxf(sacc[nb][2*r], sacc[nb][2*r+1]));
            tm = fmaxf(tm, __shfl_xor_sync(0xffffffffu, tm, 1));
            tm = fmaxf(tm, __shfl_xor_sync(0xffffffffu, tm, 2));
            const float mn = fmaxf(mrun[r], tm);
            const float al = __expf(mrun[r] - mn);
            mrun[r] = mn;
            float rs = 0.0f;
            #pragma unroll
            for (int nb = 0; nb < 8; nb++) {
                float p0 = __expf(sacc[nb][2*r]   - mn);
                float p1 = __expf(sacc[nb][2*r+1] - mn);
                sacc[nb][2*r] = p0; sacc[nb][2*r+1] = p1;
                rs += p0 + p1;
            }
            rs += __shfl_xor_sync(0xffffffffu, rs, 1);
            rs += __shfl_xor_sync(0xffffffffu, rs, 2);
            lsum[r] = lsum[r] * al + rs;
            #pragma unroll
            for (int dn = 0; dn < 8; dn++) {
                oacc[dn][2*r] *= al; oacc[dn][2*r+1] *= al;
            }
        }

        #pragma unroll
        for (int j = 0; j < 4; j++) {
            uint32_t ah[4], al4[4];
            pack_hilo(sacc[2*j][0],   sacc[2*j][1],   ah[0], al4[0]);
            pack_hilo(sacc[2*j][2],   sacc[2*j][3],   ah[1], al4[1]);
            pack_hilo(sacc[2*j+1][0], sacc[2*j+1][1], ah[2], al4[2]);
            pack_hilo(sacc[2*j+1][2], sacc[2*j+1][3], ah[3], al4[3]);
            #pragma unroll
            for (int dnp = 0; dnp < 4; dnp++) {
                uint32_t vh4[4], vl4[4];
                uint32_t va = smem_u32(Vhs + (j * 16 + t_r) * ALD + dnp * 16 + t_c);
                ldsm_x4_t(vh4[0], vh4[1], vh4[2], vh4[3], va);
                uint32_t vb = smem_u32(Vls + (j * 16 + t_r) * ALD + dnp * 16 + t_c);
                ldsm_x4_t(vl4[0], vl4[1], vl4[2], vl4[3], vb);
                #pragma unroll
                for (int hf = 0; hf < 2; hf++) {
                    const int dn = dnp * 2 + hf;
                    uint32_t bh2[2] = { vh4[hf*2], vh4[hf*2+1] };
                    uint32_t bl2[2] = { vl4[hf*2], vl4[hf*2+1] };
                    mma_bf16(oacc[dn], ah, bh2);
                    mma_bf16(oacc[dn], ah, bl2);
                    mma_bf16(oacc[dn], al4, bh2);
                }
            }
        }
    }

    const int b = bh >> 4, h = bh & 15;
    #pragma unroll
    for (int r = 0; r < 2; r++) {
        const float inv = 1.0f / lsum[r];
        const int row = q0 + w * 16 + (lane >> 2) + r * 8;
        const size_t off = (size_t)(b * TT + row) * CC + h * DD;
        #pragma unroll
        for (int dn = 0; dn < 8; dn++) {
            const int col = dn * 8 + (lane & 3) * 2;
            uint32_t vh, vl;
            pack_hilo(oacc[dn][2*r] * inv, oacc[dn][2*r+1] * inv, vh, vl);
            *(uint32_t*)(g_Ohi + off + col) = vh;
            *(uint32_t*)(g_Olo + off + col) = vl;
        }
    }
}

// ---------------------------------------------------------------------------
extern "C" void kernel_launch(void* const* d_in, const int* in_sizes, int n_in,
                              void* d_out, int out_size)
{
    const float* x     = (const float*)d_in[0];
    const float* wqkv  = (const float*)d_in[1];
    const float* wproj = (const float*)d_in[2];
    float* out = (float*)d_out;

    cudaFuncSetAttribute((const void*)attn_mma_kernel,
                         cudaFuncAttributeMaxDynamicSharedMemorySize, ATTN_SMEM_BYTES);
    cudaFuncSetAttribute((const void*)mma_gemm_kernel<0>,
                         cudaFuncAttributeMaxDynamicSharedMemorySize, GEMM_SMEM_BYTES);
    cudaFuncSetAttribute((const void*)mma_gemm_kernel<1>,
                         cudaFuncAttributeMaxDynamicSharedMemorySize, GEMM_SMEM_BYTES);

    __nv_bfloat16 *xhi, *xlo, *wqhi, *wqlo, *wphi, *wplo, *ohi, *olo;
    cudaGetSymbolAddress((void**)&xhi,  g_Xhi);  cudaGetSymbolAddress((void**)&xlo,  g_Xlo);
    cudaGetSymbolAddress((void**)&wqhi, g_Wqhi); cudaGetSymbolAddress((void**)&wqlo, g_Wqlo);
    cudaGetSymbolAddress((void**)&wphi, g_Wphi); cudaGetSymbolAddress((void**)&wplo, g_Wplo);
    cudaGetSymbolAddress((void**)&ohi,  g_Ohi);  cudaGetSymbolAddress((void**)&olo,  g_Olo);

    split_kernel<<<(MM*CC/4 + 255)/256, 256>>>(x, xhi, xlo, MM*CC/4);
    split_kernel<<<(NQKV*CC/4 + 255)/256, 256>>>(wqkv, wqhi, wqlo, NQKV*CC/4);
    split_kernel<<<(CC*CC/4 + 255)/256, 256>>>(wproj, wphi, wplo, CC*CC/4);

    mma_gemm_kernel<0><<<dim3(NQKV/128, MM/128), GEMM_THREADS, GEMM_SMEM_BYTES>>>(
        xhi, xlo, wqhi, wqlo, nullptr);

    attn_mma_kernel<<<dim3(TT/AQT, BB*HH), 256, ATTN_SMEM_BYTES>>>();

    mma_gemm_kernel<1><<<dim3(CC/128, MM/128), GEMM_THREADS, GEMM_SMEM_BYTES>>>(
        ohi, olo, wphi, wplo, out);
}

// round 7
// speedup vs baseline: 2.5736x; 1.0616x over previous
#include <cuda_runtime.h>
#include <cuda_bf16.h>
#include <cstdint>
#include <math.h>

// Problem constants
#define BB 4
#define TT 2048
#define CC 1024
#define HH 16
#define DD 64
#define MM (BB*TT)          // 8192
#define NQKV (3*CC)         // 3072

// ---------------------------------------------------------------------------
// Scratch (__device__ globals; no allocation allowed)
// ---------------------------------------------------------------------------
__device__ __nv_bfloat16 g_Qhi[BB*HH*TT*DD], g_Qlo[BB*HH*TT*DD];
__device__ __nv_bfloat16 g_Khi[BB*HH*TT*DD], g_Klo[BB*HH*TT*DD];
__device__ __nv_bfloat16 g_Vhi[BB*HH*TT*DD], g_Vlo[BB*HH*TT*DD];

__device__ __nv_bfloat16 g_Xhi[MM*CC],  g_Xlo[MM*CC];
__device__ __nv_bfloat16 g_Wqhi[NQKV*CC], g_Wqlo[NQKV*CC];
__device__ __nv_bfloat16 g_Wphi[CC*CC], g_Wplo[CC*CC];
__device__ __nv_bfloat16 g_Ohi[MM*CC],  g_Olo[MM*CC];

// ---------------------------------------------------------------------------
// helpers
// ---------------------------------------------------------------------------
__device__ __forceinline__ uint32_t smem_u32(const void* p) {
    uint32_t a;
    asm("{ .reg .u64 t; cvta.to.shared.u64 t, %1; cvt.u32.u64 %0, t; }" : "=r"(a) : "l"(p));
    return a;
}
__device__ __forceinline__ void ldsm_x4(uint32_t& r0, uint32_t& r1, uint32_t& r2,
                                        uint32_t& r3, uint32_t addr) {
    asm volatile("ldmatrix.sync.aligned.m8n8.x4.shared.b16 {%0,%1,%2,%3}, [%4];"
                 : "=r"(r0), "=r"(r1), "=r"(r2), "=r"(r3) : "r"(addr));
}
__device__ __forceinline__ void ldsm_x4_t(uint32_t& r0, uint32_t& r1, uint32_t& r2,
                                          uint32_t& r3, uint32_t addr) {
    asm volatile("ldmatrix.sync.aligned.m8n8.x4.trans.shared.b16 {%0,%1,%2,%3}, [%4];"
                 : "=r"(r0), "=r"(r1), "=r"(r2), "=r"(r3) : "r"(addr));
}
__device__ __forceinline__ void mma_bf16(float* c, const uint32_t* a, const uint32_t* b) {
    asm volatile("mma.sync.aligned.m16n8k16.row.col.f32.bf16.bf16.f32 "
                 "{%0,%1,%2,%3}, {%4,%5,%6,%7}, {%8,%9}, {%0,%1,%2,%3};"
                 : "+f"(c[0]), "+f"(c[1]), "+f"(c[2]), "+f"(c[3])
                 : "r"(a[0]), "r"(a[1]), "r"(a[2]), "r"(a[3]), "r"(b[0]), "r"(b[1]));
}
__device__ __forceinline__ void cp16(uint32_t dst, const void* src) {
    asm volatile("cp.async.cg.shared.global [%0], [%1], 16;" :: "r"(dst), "l"(src));
}
#define CP_COMMIT() asm volatile("cp.async.commit_group;" ::: "memory")
#define CP_WAIT(N)  asm volatile("cp.async.wait_group %0;" :: "n"(N) : "memory")

__device__ __forceinline__ void split_f32(float x, __nv_bfloat16& hi, __nv_bfloat16& lo) {
    hi = __float2bfloat16(x);
    lo = __float2bfloat16(x - __bfloat162float(hi));
}
__device__ __forceinline__ uint32_t pack2(__nv_bfloat16 a, __nv_bfloat16 b) {
    __nv_bfloat162 t(a, b);
    return *reinterpret_cast<uint32_t*>(&t);
}
__device__ __forceinline__ void pack_hilo(float x, float y, uint32_t& hi, uint32_t& lo) {
    __nv_bfloat16 hx, lx, hy, ly;
    split_f32(x, hx, lx); split_f32(y, hy, ly);
    hi = pack2(hx, hy); lo = pack2(lx, ly);
}

// ---------------------------------------------------------------------------
// fp32 -> (hi,lo) bf16 split
// ---------------------------------------------------------------------------
__global__ __launch_bounds__(256) void split_kernel(const float* __restrict__ src,
                                                    __nv_bfloat16* __restrict__ hi,
                                                    __nv_bfloat16* __restrict__ lo, int n4)
{
    int i = blockIdx.x * blockDim.x + threadIdx.x;
    if (i >= n4) return;
    float4 v = ((const float4*)src)[i];
    __nv_bfloat16 h[4], l[4];
    split_f32(v.x, h[0], l[0]); split_f32(v.y, h[1], l[1]);
    split_f32(v.z, h[2], l[2]); split_f32(v.w, h[3], l[3]);
    ((__nv_bfloat162*)hi)[i*2+0] = __nv_bfloat162(h[0], h[1]);
    ((__nv_bfloat162*)hi)[i*2+1] = __nv_bfloat162(h[2], h[3]);
    ((__nv_bfloat162*)lo)[i*2+0] = __nv_bfloat162(l[0], l[1]);
    ((__nv_bfloat162*)lo)[i*2+1] = __nv_bfloat162(l[2], l[3]);
}

// ---------------------------------------------------------------------------
// HMMA split-bf16 GEMM, 512 threads / 16 warps, warp tile 32x32.
// 128x128 CTA tile, BK=64, 3-stage cp.async (one barrier per 64-K chunk),
// pass-outer MMA ordering (no same-accumulator back-to-back chains).
// MODE 0: split C -> g_{Q,K,V}{hi,lo} [B,H,T,D] (Q scaled 0.125). MODE 1: fp32 out.
// ---------------------------------------------------------------------------
#define BKG 64
#define LDG_ 72                    // row pitch in bf16 (144 B = 9*16B, conflict-free)
#define TILEG (128*LDG_)           // 9216 ele
#define STAGEG (4*TILEG)           // 36864 ele
#define NSTG 3
#define GEMM_SMEM_BYTES (NSTG*STAGEG*2)   // 221184 B
#define GEMM_THREADS 512

template<int MODE>
__global__ __launch_bounds__(GEMM_THREADS, 1) void mma_gemm_kernel(
    const __nv_bfloat16* __restrict__ Ahi, const __nv_bfloat16* __restrict__ Alo,
    const __nv_bfloat16* __restrict__ Bhi, const __nv_bfloat16* __restrict__ Blo,
    float* __restrict__ out)
{
    extern __shared__ __nv_bfloat16 sm[];
    const uint32_t smb = smem_u32(sm);
    const int tid = threadIdx.x;
    const int lane = tid & 31, wid = tid >> 5;     // wid 0..15
    const int wm = (wid >> 2) * 32;
    const int wn = (wid & 3) * 32;
    const int n0 = blockIdx.x * 128;
    const int m0 = blockIdx.y * 128;

    const __nv_bfloat16* srcs[4] = {
        Ahi + (size_t)m0 * CC, Alo + (size_t)m0 * CC,
        Bhi + (size_t)n0 * CC, Blo + (size_t)n0 * CC };

    const int NCH = CC / BKG;   // 16

    float acc[2][4][4];
    #pragma unroll
    for (int a = 0; a < 2; a++)
        #pragma unroll
        for (int b = 0; b < 4; b++)
            #pragma unroll
            for (int c = 0; c < 4; c++) acc[a][b][c] = 0.0f;

    const int a_m = ((lane >> 3) & 1) * 8 + (lane & 7);
    const int a_k = (lane >> 4) * 8;
    const int b_n = (lane >> 4) * 8 + (lane & 7);
    const int b_k = ((lane >> 3) & 1) * 8;

    // issue one 64-K chunk (4 tiles of 128x64 bf16) into a stage; 8 cp16/thread
    auto issue_chunk = [&](int ch) {
        const uint32_t sbase = smb + (uint32_t)(ch % NSTG) * (STAGEG * 2);
        const int k0 = ch * BKG;
        #pragma unroll
        for (int l = 0; l < 8; l++) {
            const int o = l * GEMM_THREADS + tid;     // 0..4095
            const int tile = o >> 10;
            const int r = (o >> 3) & 127;
            const int c = (o & 7) * 8;
            cp16(sbase + (uint32_t)(tile * TILEG + r * LDG_ + c) * 2,
                 srcs[tile] + (size_t)r * CC + k0 + c);
        }
    };

    issue_chunk(0); CP_COMMIT();
    issue_chunk(1); CP_COMMIT();

    for (int ch = 0; ch < NCH; ch++) {
        CP_WAIT(1);
        __syncthreads();
        if (ch + 2 < NCH) issue_chunk(ch + 2);
        CP_COMMIT();

        const __nv_bfloat16* buf = sm + (ch % NSTG) * STAGEG;

        #pragma unroll
        for (int kk = 0; kk < BKG; kk += 16) {
            uint32_t aH[2][4], aL[2][4], bH[2][4], bL[2][4];
            #pragma unroll
            for (int mi = 0; mi < 2; mi++) {
                const int m = wm + mi * 16 + a_m;
                uint32_t ad = smem_u32(buf + m * LDG_ + kk + a_k);
                ldsm_x4(aH[mi][0], aH[mi][1], aH[mi][2], aH[mi][3], ad);
                ldsm_x4(aL[mi][0], aL[mi][1], aL[mi][2], aL[mi][3], ad + TILEG * 2);
            }
            #pragma unroll
            for (int ni = 0; ni < 2; ni++) {
                const int n = wn + ni * 16 + b_n;
                uint32_t bd = smem_u32(buf + 2 * TILEG + n * LDG_ + kk + b_k);
                ldsm_x4(bH[ni][0], bH[ni][1], bH[ni][2], bH[ni][3], bd);
                ldsm_x4(bL[ni][0], bL[ni][1], bL[ni][2], bL[ni][3], bd + TILEG * 2);
            }
            // pass-outer ordering: consecutive MMAs hit distinct accumulators
            #pragma unroll
            for (int mi = 0; mi < 2; mi++)
                #pragma unroll
                for (int nj = 0; nj < 4; nj++) {
                    uint32_t bh[2] = { bH[nj >> 1][(nj & 1) * 2], bH[nj >> 1][(nj & 1) * 2 + 1] };
                    mma_bf16(acc[mi][nj], aH[mi], bh);
                }
            #pragma unroll
            for (int mi = 0; mi < 2; mi++)
                #pragma unroll
                for (int nj = 0; nj < 4; nj++) {
                    uint32_t bl[2] = { bL[nj >> 1][(nj & 1) * 2], bL[nj >> 1][(nj & 1) * 2 + 1] };
                    mma_bf16(acc[mi][nj], aH[mi], bl);
                }
            #pragma unroll
            for (int mi = 0; mi < 2; mi++)
                #pragma unroll
                for (int nj = 0; nj < 4; nj++) {
                    uint32_t bh[2] = { bH[nj >> 1][(nj & 1) * 2], bH[nj >> 1][(nj & 1) * 2 + 1] };
                    mma_bf16(acc[mi][nj], aL[mi], bh);
                }
        }
    }

    // epilogue
    if (MODE == 0) {
        const int which = n0 >> 10;
        __nv_bfloat16* dhi = (which == 0) ? g_Qhi : ((which == 1) ? g_Khi : g_Vhi);
        __nv_bfloat16* dlo = (which == 0) ? g_Qlo : ((which == 1) ? g_Klo : g_Vlo);
        const float scl = (which == 0) ? 0.125f : 1.0f;
        #pragma unroll
        for (int mi = 0; mi < 2; mi++)
            #pragma unroll
            for (int nj = 0; nj < 4; nj++) {
                const int row0 = m0 + wm + mi * 16 + (lane >> 2);
                const int col  = n0 + wn + nj * 8 + (lane & 3) * 2;
                const int o = col & 1023, hd = o >> 6, d = o & 63;
                #pragma unroll
                for (int h = 0; h < 2; h++) {
                    const int row = row0 + h * 8;
                    const int b = row >> 11, t = row & 2047;
                    uint32_t vh, vl;
                    pack_hilo(acc[mi][nj][h*2] * scl, acc[mi][nj][h*2+1] * scl, vh, vl);
                    size_t off = ((size_t)(b * HH + hd) * TT + t) * DD + d;
                    *(uint32_t*)(dhi + off) = vh;
                    *(uint32_t*)(dlo + off) = vl;
                }
            }
    } else {
        #pragma unroll
        for (int mi = 0; mi < 2; mi++)
            #pragma unroll
            for (int nj = 0; nj < 4; nj++) {
                const int row0 = m0 + wm + mi * 16 + (lane >> 2);
                const int col  = n0 + wn + nj * 8 + (lane & 3) * 2;
                #pragma unroll
                for (int h = 0; h < 2; h++) {
                    const int row = row0 + h * 8;
                    float2 v = make_float2(acc[mi][nj][h*2], acc[mi][nj][h*2+1]);
                    *(float2*)(out + (size_t)row * CC + col) = v;
                }
            }
    }
}

// ---------------------------------------------------------------------------
// Tensor-core flash attention (causal), cp.async 3-stage K/V pipeline,
// ldmatrix.trans for V. 128 q/CTA, KTILE=64, 8 warps. (unchanged)
// ---------------------------------------------------------------------------
#define AQT 128
#define AKT 64
#define ALD 72

struct AttnSmem {
    __nv_bfloat16 Q[2][AQT*ALD];          // hi, lo
    __nv_bfloat16 KV[3][4][AKT*ALD];      // stage, {Khi,Klo,Vhi,Vlo}
};
#define ATTN_SMEM_BYTES ((int)sizeof(AttnSmem))   // 147456

__global__ __launch_bounds__(256, 1) void attn_mma_kernel()
{
    extern __shared__ char smraw[];
    AttnSmem& s = *(AttnSmem*)smraw;

    const int tid = threadIdx.x, lane = tid & 31, w = tid >> 5;
    const int bh = blockIdx.y;
    const int qi = gridDim.x - 1 - blockIdx.x;
    const int q0 = qi * AQT;
    const size_t base = (size_t)bh * TT * DD;
    const __nv_bfloat16* kvsrc[4] = { g_Khi + base, g_Klo + base, g_Vhi + base, g_Vlo + base };
    const __nv_bfloat16 *Qh = g_Qhi + base, *Ql = g_Qlo + base;

    const int nk = 2 * qi + 2;

    const int kr0 = tid >> 3, kr1 = 32 + (tid >> 3);
    const int kc = (tid & 7) * 8;

    auto issue_kv = [&](int kt) {
        const int st = kt % 3;
        const int k0 = kt * AKT;
        #pragma unroll
        for (int t = 0; t < 4; t++) {
            cp16(smem_u32(&s.KV[st][t][kr0 * ALD + kc]),
                 kvsrc[t] + (size_t)(k0 + kr0) * DD + kc);
            cp16(smem_u32(&s.KV[st][t][kr1 * ALD + kc]),
                 kvsrc[t] + (size_t)(k0 + kr1) * DD + kc);
        }
    };

    issue_kv(0); CP_COMMIT();
    issue_kv(1); CP_COMMIT();

    #pragma unroll
    for (int l = 0; l < 4; l++) {
        int idx = l * 256 + tid;
        int r = idx >> 3, d0 = (idx & 7) * 8;
        *(uint4*)&s.Q[0][r * ALD + d0] = *(const uint4*)(Qh + (size_t)(q0 + r) * DD + d0);
        *(uint4*)&s.Q[1][r * ALD + d0] = *(const uint4*)(Ql + (size_t)(q0 + r) * DD + d0);
    }
    __syncthreads();

    const int a_m = ((lane >> 3) & 1) * 8 + (lane & 7);
    const int a_k = (lane >> 4) * 8;
    const int b_n = (lane >> 4) * 8 + (lane & 7);
    const int b_k = ((lane >> 3) & 1) * 8;
    const int t_r = ((lane >> 3) & 1) * 8 + (lane & 7);
    const int t_c = (lane >> 4) * 8;

    uint32_t qh[4][4], ql[4][4];
    #pragma unroll
    for (int ks = 0; ks < 4; ks++) {
        uint32_t qa = smem_u32(&s.Q[0][(w * 16 + a_m) * ALD + ks * 16 + a_k]);
        ldsm_x4(qh[ks][0], qh[ks][1], qh[ks][2], qh[ks][3], qa);
        uint32_t qb = smem_u32(&s.Q[1][(w * 16 + a_m) * ALD + ks * 16 + a_k]);
        ldsm_x4(ql[ks][0], ql[ks][1], ql[ks][2], ql[ks][3], qb);
    }

    float oacc[8][4];
    #pragma unroll
    for (int i = 0; i < 8; i++)
        #pragma unroll
        for (int j = 0; j < 4; j++) oacc[i][j] = 0.0f;
    float mrun[2] = { -1e30f, -1e30f }, lsum[2] = { 0.0f, 0.0f };

    const int qrow = q0 + w * 16 + (lane >> 2);

    for (int kt = 0; kt < nk; kt++) {
        const int k0 = kt * AKT;
        CP_WAIT(1);
        __syncthreads();
        if (kt + 2 < nk) issue_kv(kt + 2);
        CP_COMMIT();

        const int st = kt % 3;
        const __nv_bfloat16* Khs = s.KV[st][0];
        const __nv_bfloat16* Kls = s.KV[st][1];
        const __nv_bfloat16* Vhs = s.KV[st][2];
        const __nv_bfloat16* Vls = s.KV[st][3];

        float sacc[8][4];
        #pragma unroll
        for (int i = 0; i < 8; i++)
            #pragma unroll
            for (int j = 0; j < 4; j++) sacc[i][j] = 0.0f;

        #pragma unroll
        for (int nbp = 0; nbp < 4; nbp++) {
            #pragma unroll
            for (int ks = 0; ks < 4; ks++) {
                uint32_t kh4[4], kl4[4];
                uint32_t ka = smem_u32(Khs + (nbp * 16 + b_n) * ALD + ks * 16 + b_k);
                ldsm_x4(kh4[0], kh4[1], kh4[2], kh4[3], ka);
                uint32_t kb = smem_u32(Kls + (nbp * 16 + b_n) * ALD + ks * 16 + b_k);
                ldsm_x4(kl4[0], kl4[1], kl4[2], kl4[3], kb);
                #pragma unroll
                for (int hf = 0; hf < 2; hf++) {
                    const int nb = nbp * 2 + hf;
                    uint32_t bh2[2] = { kh4[hf*2], kh4[hf*2+1] };
                    uint32_t bl2[2] = { kl4[hf*2], kl4[hf*2+1] };
                    mma_bf16(sacc[nb], qh[ks], bh2);
                    mma_bf16(sacc[nb], qh[ks], bl2);
                    mma_bf16(sacc[nb], ql[ks], bh2);
                }
            }
        }

        if (k0 + 63 > qrow) {
            #pragma unroll
            for (int nb = 0; nb < 8; nb++)
                #pragma unroll
                for (int c = 0; c < 4; c++) {
                    const int kg = k0 + nb * 8 + (lane & 3) * 2 + (c & 1);
                    const int qg = qrow + ((c >= 2) ? 8 : 0);
                    if (kg > qg) sacc[nb][c] = -1e30f;
                }
        }

        #pragma unroll
        for (int r = 0; r < 2; r++) {
            float tm = -1e30f;
            #pragma unroll
            for (int nb = 0; nb < 8; nb++)
                tm = fmaxf(tm, fmaxf(sacc[nb][2*r], sacc[nb][2*r+1]));
            tm = fmaxf(tm, __shfl_xor_sync(0xffffffffu, tm, 1));
            tm = fmaxf(tm, __shfl_xor_sync(0xffffffffu, tm, 2));
            const float mn = fmaxf(mrun[r], tm);
            const float al = __expf(mrun[r] - mn);
            mrun[r] = mn;
            float rs = 0.0f;
            #pragma unroll
            for (int nb = 0; nb < 8; nb++) {
                float p0 = __expf(sacc[nb][2*r]   - mn);
                float p1 = __expf(sacc[nb][2*r+1] - mn);
                sacc[nb][2*r] = p0; sacc[nb][2*r+1] = p1;
                rs += p0 + p1;
            }
            rs += __shfl_xor_sync(0xffffffffu, rs, 1);
            rs += __shfl_xor_sync(0xffffffffu, rs, 2);
            lsum[r] = lsum[r] * al + rs;
            #pragma unroll
            for (int dn = 0; dn < 8; dn++) {
                oacc[dn][2*r] *= al; oacc[dn][2*r+1] *= al;
            }
        }

        #pragma unroll
        for (int j = 0; j < 4; j++) {
            uint32_t ah[4], al4[4];
            pack_hilo(sacc[2*j][0],   sacc[2*j][1],   ah[0], al4[0]);
            pack_hilo(sacc[2*j][2],   sacc[2*j][3],   ah[1], al4[1]);
            pack_hilo(sacc[2*j+1][0], sacc[2*j+1][1], ah[2], al4[2]);
            pack_hilo(sacc[2*j+1][2], sacc[2*j+1][3], ah[3], al4[3]);
            #pragma unroll
            for (int dnp = 0; dnp < 4; dnp++) {
                uint32_t vh4[4], vl4[4];
                uint32_t va = smem_u32(Vhs + (j * 16 + t_r) * ALD + dnp * 16 + t_c);
                ldsm_x4_t(vh4[0], vh4[1], vh4[2], vh4[3], va);
                uint32_t vb = smem_u32(Vls + (j * 16 + t_r) * ALD + dnp * 16 + t_c);
                ldsm_x4_t(vl4[0], vl4[1], vl4[2], vl4[3], vb);
                #pragma unroll
                for (int hf = 0; hf < 2; hf++) {
                    const int dn = dnp * 2 + hf;
                    uint32_t bh2[2] = { vh4[hf*2], vh4[hf*2+1] };
                    uint32_t bl2[2] = { vl4[hf*2], vl4[hf*2+1] };
                    mma_bf16(oacc[dn], ah, bh2);
                    mma_bf16(oacc[dn], ah, bl2);
                    mma_bf16(oacc[dn], al4, bh2);
                }
            }
        }
    }

    const int b = bh >> 4, h = bh & 15;
    #pragma unroll
    for (int r = 0; r < 2; r++) {
        const float inv = 1.0f / lsum[r];
        const int row = q0 + w * 16 + (lane >> 2) + r * 8;
        const size_t off = (size_t)(b * TT + row) * CC + h * DD;
        #pragma unroll
        for (int dn = 0; dn < 8; dn++) {
            const int col = dn * 8 + (lane & 3) * 2;
            uint32_t vh, vl;
            pack_hilo(oacc[dn][2*r] * inv, oacc[dn][2*r+1] * inv, vh, vl);
            *(uint32_t*)(g_Ohi + off + col) = vh;
            *(uint32_t*)(g_Olo + off + col) = vl;
        }
    }
}

// ---------------------------------------------------------------------------
extern "C" void kernel_launch(void* const* d_in, const int* in_sizes, int n_in,
                              void* d_out, int out_size)
{
    const float* x     = (const float*)d_in[0];
    const float* wqkv  = (const float*)d_in[1];
    const float* wproj = (const float*)d_in[2];
    float* out = (float*)d_out;

    cudaFuncSetAttribute((const void*)attn_mma_kernel,
                         cudaFuncAttributeMaxDynamicSharedMemorySize, ATTN_SMEM_BYTES);
    cudaFuncSetAttribute((const void*)mma_gemm_kernel<0>,
                         cudaFuncAttributeMaxDynamicSharedMemorySize, GEMM_SMEM_BYTES);
    cudaFuncSetAttribute((const void*)mma_gemm_kernel<1>,
                         cudaFuncAttributeMaxDynamicSharedMemorySize, GEMM_SMEM_BYTES);

    __nv_bfloat16 *xhi, *xlo, *wqhi, *wqlo, *wphi, *wplo, *ohi, *olo;
    cudaGetSymbolAddress((void**)&xhi,  g_Xhi);  cudaGetSymbolAddress((void**)&xlo,  g_Xlo);
    cudaGetSymbolAddress((void**)&wqhi, g_Wqhi); cudaGetSymbolAddress((void**)&wqlo, g_Wqlo);
    cudaGetSymbolAddress((void**)&wphi, g_Wphi); cudaGetSymbolAddress((void**)&wplo, g_Wplo);
    cudaGetSymbolAddress((void**)&ohi,  g_Ohi);  cudaGetSymbolAddress((void**)&olo,  g_Olo);

    split_kernel<<<(MM*CC/4 + 255)/256, 256>>>(x, xhi, xlo, MM*CC/4);
    split_kernel<<<(NQKV*CC/4 + 255)/256, 256>>>(wqkv, wqhi, wqlo, NQKV*CC/4);
    split_kernel<<<(CC*CC/4 + 255)/256, 256>>>(wproj, wphi, wplo, CC*CC/4);

    mma_gemm_kernel<0><<<dim3(NQKV/128, MM/128), GEMM_THREADS, GEMM_SMEM_BYTES>>>(
        xhi, xlo, wqhi, wqlo, nullptr);

    attn_mma_kernel<<<dim3(TT/AQT, BB*HH), 256, ATTN_SMEM_BYTES>>>();

    mma_gemm_kernel<1><<<dim3(CC/128, MM/128), GEMM_THREADS, GEMM_SMEM_BYTES>>>(
        ohi, olo, wphi, wplo, out);
}

// round 8
// speedup vs baseline: 3.4162x; 1.3274x over previous
#include <cuda_runtime.h>
#include <cuda_fp16.h>
#include <cstdint>
#include <math.h>

// Problem constants
#define BB 4
#define TT 2048
#define CC 1024
#define HH 16
#define DD 64
#define MM (BB*TT)          // 8192
#define NQKV (3*CC)         // 3072

// ---------------------------------------------------------------------------
// Scratch (__device__ globals; no allocation allowed)
// ---------------------------------------------------------------------------
__device__ __half g_Qh[BB*HH*TT*DD];                      // fp16, pre-scaled
__device__ __half g_Kh[BB*HH*TT*DD], g_Kl[BB*HH*TT*DD];   // fp16 hi/lo
__device__ __half g_Vh[BB*HH*TT*DD], g_Vl[BB*HH*TT*DD];
__device__ __half g_Xh[MM*CC];                            // x as fp16 (hi only)
__device__ __half g_Wqh[NQKV*CC], g_Wql[NQKV*CC];         // w_qkv hi/lo
__device__ __half g_Wph[CC*CC],  g_Wpl[CC*CC];            // w_proj hi/lo
__device__ __half g_Oh[MM*CC];                            // attn out (hi only)

// ---------------------------------------------------------------------------
// helpers
// ---------------------------------------------------------------------------
__device__ __forceinline__ uint32_t smem_u32(const void* p) {
    uint32_t a;
    asm("{ .reg .u64 t; cvta.to.shared.u64 t, %1; cvt.u32.u64 %0, t; }" : "=r"(a) : "l"(p));
    return a;
}
__device__ __forceinline__ void ldsm_x4(uint32_t& r0, uint32_t& r1, uint32_t& r2,
                                        uint32_t& r3, uint32_t addr) {
    asm volatile("ldmatrix.sync.aligned.m8n8.x4.shared.b16 {%0,%1,%2,%3}, [%4];"
                 : "=r"(r0), "=r"(r1), "=r"(r2), "=r"(r3) : "r"(addr));
}
__device__ __forceinline__ void ldsm_x4_t(uint32_t& r0, uint32_t& r1, uint32_t& r2,
                                          uint32_t& r3, uint32_t addr) {
    asm volatile("ldmatrix.sync.aligned.m8n8.x4.trans.shared.b16 {%0,%1,%2,%3}, [%4];"
                 : "=r"(r0), "=r"(r1), "=r"(r2), "=r"(r3) : "r"(addr));
}
__device__ __forceinline__ void mma_f16(float* c, const uint32_t* a, const uint32_t* b) {
    asm volatile("mma.sync.aligned.m16n8k16.row.col.f32.f16.f16.f32 "
                 "{%0,%1,%2,%3}, {%4,%5,%6,%7}, {%8,%9}, {%0,%1,%2,%3};"
                 : "+f"(c[0]), "+f"(c[1]), "+f"(c[2]), "+f"(c[3])
                 : "r"(a[0]), "r"(a[1]), "r"(a[2]), "r"(a[3]), "r"(b[0]), "r"(b[1]));
}
__device__ __forceinline__ void cp16(uint32_t dst, const void* src) {
    asm volatile("cp.async.cg.shared.global [%0], [%1], 16;" :: "r"(dst), "l"(src));
}
#define CP_COMMIT() asm volatile("cp.async.commit_group;" ::: "memory")
#define CP_WAIT(N)  asm volatile("cp.async.wait_group %0;" :: "n"(N) : "memory")

__device__ __forceinline__ void splith(float x, __half& h, __half& l) {
    h = __float2half_rn(x);
    l = __float2half_rn(x - __half2float(h));
}
__device__ __forceinline__ uint32_t packh(__half a, __half b) {
    __half2 t(a, b);                       // a -> low half
    return *reinterpret_cast<uint32_t*>(&t);
}
__device__ __forceinline__ uint32_t packf2(float x, float y) {
    __half2 t = __floats2half2_rn(x, y);   // x -> low half
    return *reinterpret_cast<uint32_t*>(&t);
}

// ---------------------------------------------------------------------------
// conversion kernels
// ---------------------------------------------------------------------------
__global__ __launch_bounds__(256) void tohalf_kernel(const float* __restrict__ src,
                                                     __half* __restrict__ dst, int n4)
{
    int i = blockIdx.x * blockDim.x + threadIdx.x;
    if (i >= n4) return;
    float4 v = ((const float4*)src)[i];
    ((uint32_t*)dst)[i*2+0] = packf2(v.x, v.y);
    ((uint32_t*)dst)[i*2+1] = packf2(v.z, v.w);
}

__global__ __launch_bounds__(256) void splith_kernel(const float* __restrict__ src,
                                                     __half* __restrict__ hi,
                                                     __half* __restrict__ lo, int n4)
{
    int i = blockIdx.x * blockDim.x + threadIdx.x;
    if (i >= n4) return;
    float4 v = ((const float4*)src)[i];
    __half h[4], l[4];
    splith(v.x, h[0], l[0]); splith(v.y, h[1], l[1]);
    splith(v.z, h[2], l[2]); splith(v.w, h[3], l[3]);
    ((uint32_t*)hi)[i*2+0] = packh(h[0], h[1]);
    ((uint32_t*)hi)[i*2+1] = packh(h[2], h[3]);
    ((uint32_t*)lo)[i*2+0] = packh(l[0], l[1]);
    ((uint32_t*)lo)[i*2+1] = packh(l[2], l[3]);
}

// ---------------------------------------------------------------------------
// HMMA fp16 2-pass GEMM: C[m,n] = sum_k Ah[m,k]*(Bh+Bl)[n,k]
// 512 threads / 16 warps, warp tile 32x32, CTA 128x128, BK=64, 3-stage cp.async.
// Operand tiles per chunk: Ah, Bh, Bl (3).
// MODE 0: Q -> fp16 scaled, K/V -> fp16 hi/lo splits, [B,H,T,D]. MODE 1: fp32 out.
// ---------------------------------------------------------------------------
#define BKG 64
#define LDG_ 72
#define TILEG (128*LDG_)           // 9216 halves
#define STAGEG (3*TILEG)           // 27648 halves (Ah,Bh,Bl)
#define NSTG 3
#define GEMM_SMEM_BYTES (NSTG*STAGEG*2)   // 165888 B
#define GEMM_THREADS 512

template<int MODE>
__global__ __launch_bounds__(GEMM_THREADS, 1) void mma_gemm_kernel(
    const __half* __restrict__ Ah, const __half* __restrict__ Bh,
    const __half* __restrict__ Bl, float* __restrict__ out)
{
    extern __shared__ __half sm[];
    const uint32_t smb = smem_u32(sm);
    const int tid = threadIdx.x;
    const int lane = tid & 31, wid = tid >> 5;
    const int wm = (wid >> 2) * 32;
    const int wn = (wid & 3) * 32;
    const int n0 = blockIdx.x * 128;
    const int m0 = blockIdx.y * 128;

    const __half* srcs[3] = {
        Ah + (size_t)m0 * CC, Bh + (size_t)n0 * CC, Bl + (size_t)n0 * CC };

    const int NCH = CC / BKG;   // 16

    float acc[2][4][4];
    #pragma unroll
    for (int a = 0; a < 2; a++)
        #pragma unroll
        for (int b = 0; b < 4; b++)
            #pragma unroll
            for (int c = 0; c < 4; c++) acc[a][b][c] = 0.0f;

    const int a_m = ((lane >> 3) & 1) * 8 + (lane & 7);
    const int a_k = (lane >> 4) * 8;
    const int b_n = (lane >> 4) * 8 + (lane & 7);
    const int b_k = ((lane >> 3) & 1) * 8;

    // one 64-K chunk = 3 tiles of 128x64 fp16; 6 cp16/thread
    auto issue_chunk = [&](int ch) {
        const uint32_t sbase = smb + (uint32_t)(ch % NSTG) * (STAGEG * 2);
        const int k0 = ch * BKG;
        #pragma unroll
        for (int l = 0; l < 6; l++) {
            const int o = l * GEMM_THREADS + tid;     // 0..3071
            const int tile = o >> 10;
            const int r = (o >> 3) & 127;
            const int c = (o & 7) * 8;
            cp16(sbase + (uint32_t)(tile * TILEG + r * LDG_ + c) * 2,
                 srcs[tile] + (size_t)r * CC + k0 + c);
        }
    };

    issue_chunk(0); CP_COMMIT();
    issue_chunk(1); CP_COMMIT();

    for (int ch = 0; ch < NCH; ch++) {
        CP_WAIT(1);
        __syncthreads();
        if (ch + 2 < NCH) issue_chunk(ch + 2);
        CP_COMMIT();

        const __half* buf = sm + (ch % NSTG) * STAGEG;

        #pragma unroll
        for (int kk = 0; kk < BKG; kk += 16) {
            uint32_t aH[2][4], bH[2][4], bL[2][4];
            #pragma unroll
            for (int mi = 0; mi < 2; mi++) {
                const int m = wm + mi * 16 + a_m;
                uint32_t ad = smem_u32(buf + m * LDG_ + kk + a_k);
                ldsm_x4(aH[mi][0], aH[mi][1], aH[mi][2], aH[mi][3], ad);
            }
            #pragma unroll
            for (int ni = 0; ni < 2; ni++) {
                const int n = wn + ni * 16 + b_n;
                uint32_t bd = smem_u32(buf + TILEG + n * LDG_ + kk + b_k);
                ldsm_x4(bH[ni][0], bH[ni][1], bH[ni][2], bH[ni][3], bd);
                ldsm_x4(bL[ni][0], bL[ni][1], bL[ni][2], bL[ni][3], bd + TILEG * 2);
            }
            // pass-outer: consecutive MMAs hit distinct accumulators
            #pragma unroll
            for (int mi = 0; mi < 2; mi++)
                #pragma unroll
                for (int nj = 0; nj < 4; nj++) {
                    uint32_t bh[2] = { bH[nj >> 1][(nj & 1) * 2], bH[nj >> 1][(nj & 1) * 2 + 1] };
                    mma_f16(acc[mi][nj], aH[mi], bh);
                }
            #pragma unroll
            for (int mi = 0; mi < 2; mi++)
                #pragma unroll
                for (int nj = 0; nj < 4; nj++) {
                    uint32_t bl[2] = { bL[nj >> 1][(nj & 1) * 2], bL[nj >> 1][(nj & 1) * 2 + 1] };
                    mma_f16(acc[mi][nj], aH[mi], bl);
                }
        }
    }

    // epilogue
    if (MODE == 0) {
        const int which = n0 >> 10;
        #pragma unroll
        for (int mi = 0; mi < 2; mi++)
            #pragma unroll
            for (int nj = 0; nj < 4; nj++) {
                const int row0 = m0 + wm + mi * 16 + (lane >> 2);
                const int col  = n0 + wn + nj * 8 + (lane & 3) * 2;
                const int o = col & 1023, hd = o >> 6, d = o & 63;
                #pragma unroll
                for (int h = 0; h < 2; h++) {
                    const int row = row0 + h * 8;
                    const int b = row >> 11, t = row & 2047;
                    const size_t off = ((size_t)(b * HH + hd) * TT + t) * DD + d;
                    const float x0 = acc[mi][nj][h*2], x1 = acc[mi][nj][h*2+1];
                    if (which == 0) {
                        *(uint32_t*)(g_Qh + off) = packf2(x0 * 0.125f, x1 * 0.125f);
                    } else {
                        __half* dh = (which == 1) ? g_Kh : g_Vh;
                        __half* dl = (which == 1) ? g_Kl : g_Vl;
                        __half h0, l0, h1, l1;
                        splith(x0, h0, l0); splith(x1, h1, l1);
                        *(uint32_t*)(dh + off) = packh(h0, h1);
                        *(uint32_t*)(dl + off) = packh(l0, l1);
                    }
                }
            }
    } else {
        #pragma unroll
        for (int mi = 0; mi < 2; mi++)
            #pragma unroll
            for (int nj = 0; nj < 4; nj++) {
                const int row0 = m0 + wm + mi * 16 + (lane >> 2);
                const int col  = n0 + wn + nj * 8 + (lane & 3) * 2;
                #pragma unroll
                for (int h = 0; h < 2; h++) {
                    const int row = row0 + h * 8;
                    float2 v = make_float2(acc[mi][nj][h*2], acc[mi][nj][h*2+1]);
                    *(float2*)(out + (size_t)row * CC + col) = v;
                }
            }
    }
}

// ---------------------------------------------------------------------------
// fp16 2-pass tensor-core flash attention (causal).
// Q fp16 (hi only, pre-scaled); K,V fp16 hi/lo; P fp16 hi only.
// 128 q/CTA, KTILE=64, 8 warps, cp.async 3-stage K/V pipeline.
// ---------------------------------------------------------------------------
#define AQT 128
#define AKT 64
#define ALD 72

struct AttnSmem {
    __half Q[AQT*ALD];                 // fp16 Q (scaled)
    __half KV[3][4][AKT*ALD];          // stage, {Kh,Kl,Vh,Vl}
};
#define ATTN_SMEM_BYTES ((int)sizeof(AttnSmem))   // 129024

__global__ __launch_bounds__(256, 1) void attn_mma_kernel()
{
    extern __shared__ char smraw[];
    AttnSmem& s = *(AttnSmem*)smraw;

    const int tid = threadIdx.x, lane = tid & 31, w = tid >> 5;
    const int bh = blockIdx.y;
    const int qi = gridDim.x - 1 - blockIdx.x;
    const int q0 = qi * AQT;
    const size_t base = (size_t)bh * TT * DD;
    const __half* kvsrc[4] = { g_Kh + base, g_Kl + base, g_Vh + base, g_Vl + base };
    const __half* Qsrc = g_Qh + base;

    const int nk = 2 * qi + 2;

    const int kr0 = tid >> 3, kr1 = 32 + (tid >> 3);
    const int kc = (tid & 7) * 8;

    auto issue_kv = [&](int kt) {
        const int st = kt % 3;
        const int k0 = kt * AKT;
        #pragma unroll
        for (int t = 0; t < 4; t++) {
            cp16(smem_u32(&s.KV[st][t][kr0 * ALD + kc]),
                 kvsrc[t] + (size_t)(k0 + kr0) * DD + kc);
            cp16(smem_u32(&s.KV[st][t][kr1 * ALD + kc]),
                 kvsrc[t] + (size_t)(k0 + kr1) * DD + kc);
        }
    };

    issue_kv(0); CP_COMMIT();
    issue_kv(1); CP_COMMIT();

    // Q tile -> smem (128x64 fp16 = 1024 x 16B)
    #pragma unroll
    for (int l = 0; l < 4; l++) {
        int idx = l * 256 + tid;
        int r = idx >> 3, d0 = (idx & 7) * 8;
        *(uint4*)&s.Q[r * ALD + d0] = *(const uint4*)(Qsrc + (size_t)(q0 + r) * DD + d0);
    }
    __syncthreads();

    const int a_m = ((lane >> 3) & 1) * 8 + (lane & 7);
    const int a_k = (lane >> 4) * 8;
    const int b_n = (lane >> 4) * 8 + (lane & 7);
    const int b_k = ((lane >> 3) & 1) * 8;
    const int t_r = ((lane >> 3) & 1) * 8 + (lane & 7);
    const int t_c = (lane >> 4) * 8;

    uint32_t qh[4][4];
    #pragma unroll
    for (int ks = 0; ks < 4; ks++) {
        uint32_t qa = smem_u32(&s.Q[(w * 16 + a_m) * ALD + ks * 16 + a_k]);
        ldsm_x4(qh[ks][0], qh[ks][1], qh[ks][2], qh[ks][3], qa);
    }

    float oacc[8][4];
    #pragma unroll
    for (int i = 0; i < 8; i++)
        #pragma unroll
        for (int j = 0; j < 4; j++) oacc[i][j] = 0.0f;
    float mrun[2] = { -1e30f, -1e30f }, lsum[2] = { 0.0f, 0.0f };

    const int qrow = q0 + w * 16 + (lane >> 2);

    for (int kt = 0; kt < nk; kt++) {
        const int k0 = kt * AKT;
        CP_WAIT(1);
        __syncthreads();
        if (kt + 2 < nk) issue_kv(kt + 2);
        CP_COMMIT();

        const int st = kt % 3;
        const __half* Khs = s.KV[st][0];
        const __half* Kls = s.KV[st][1];
        const __half* Vhs = s.KV[st][2];
        const __half* Vls = s.KV[st][3];

        // ---- S = Q K^T (2-pass: qh*kh + qh*kl) ----
        float sacc[8][4];
        #pragma unroll
        for (int i = 0; i < 8; i++)
            #pragma unroll
            for (int j = 0; j < 4; j++) sacc[i][j] = 0.0f;

        #pragma unroll
        for (int nbp = 0; nbp < 4; nbp++) {
            #pragma unroll
            for (int ks = 0; ks < 4; ks++) {
                uint32_t kh4[4], kl4[4];
                uint32_t ka = smem_u32(Khs + (nbp * 16 + b_n) * ALD + ks * 16 + b_k);
                ldsm_x4(kh4[0], kh4[1], kh4[2], kh4[3], ka);
                uint32_t kb = smem_u32(Kls + (nbp * 16 + b_n) * ALD + ks * 16 + b_k);
                ldsm_x4(kl4[0], kl4[1], kl4[2], kl4[3], kb);
                #pragma unroll
                for (int hf = 0; hf < 2; hf++) {
                    const int nb = nbp * 2 + hf;
                    uint32_t bh2[2] = { kh4[hf*2], kh4[hf*2+1] };
                    uint32_t bl2[2] = { kl4[hf*2], kl4[hf*2+1] };
                    mma_f16(sacc[nb], qh[ks], bh2);
                    mma_f16(sacc[nb], qh[ks], bl2);
                }
            }
        }

        // ---- causal mask ----
        if (k0 + 63 > qrow) {
            #pragma unroll
            for (int nb = 0; nb < 8; nb++)
                #pragma unroll
                for (int c = 0; c < 4; c++) {
                    const int kg = k0 + nb * 8 + (lane & 3) * 2 + (c & 1);
                    const int qg = qrow + ((c >= 2) ? 8 : 0);
                    if (kg > qg) sacc[nb][c] = -1e30f;
                }
        }

        // ---- online softmax ----
        #pragma unroll
        for (int r = 0; r < 2; r++) {
            float tm = -1e30f;
            #pragma unroll
            for (int nb = 0; nb < 8; nb++)
                tm = fmaxf(tm, fmaxf(sacc[nb][2*r], sacc[nb][2*r+1]));
            tm = fmaxf(tm, __shfl_xor_sync(0xffffffffu, tm, 1));
            tm = fmaxf(tm, __shfl_xor_sync(0xffffffffu, tm, 2));
            const float mn = fmaxf(mrun[r], tm);
            const float al = __expf(mrun[r] - mn);
            mrun[r] = mn;
            float rs = 0.0f;
            #pragma unroll
            for (int nb = 0; nb < 8; nb++) {
                float p0 = __expf(sacc[nb][2*r]   - mn);
                float p1 = __expf(sacc[nb][2*r+1] - mn);
                sacc[nb][2*r] = p0; sacc[nb][2*r+1] = p1;
                rs += p0 + p1;
            }
            rs += __shfl_xor_sync(0xffffffffu, rs, 1);
            rs += __shfl_xor_sync(0xffffffffu, rs, 2);
            lsum[r] = lsum[r] * al + rs;
            #pragma unroll
            for (int dn = 0; dn < 8; dn++) {
                oacc[dn][2*r] *= al; oacc[dn][2*r+1] *= al;
            }
        }

        // ---- O += P V (P fp16 hi only; 2-pass over V hi/lo) ----
        #pragma unroll
        for (int j = 0; j < 4; j++) {
            uint32_t ah[4];
            ah[0] = packf2(sacc[2*j][0],   sacc[2*j][1]);
            ah[1] = packf2(sacc[2*j][2],   sacc[2*j][3]);
            ah[2] = packf2(sacc[2*j+1][0], sacc[2*j+1][1]);
            ah[3] = packf2(sacc[2*j+1][2], sacc[2*j+1][3]);
            #pragma unroll
            for (int dnp = 0; dnp < 4; dnp++) {
                uint32_t vh4[4], vl4[4];
                uint32_t va = smem_u32(Vhs + (j * 16 + t_r) * ALD + dnp * 16 + t_c);
                ldsm_x4_t(vh4[0], vh4[1], vh4[2], vh4[3], va);
                uint32_t vb = smem_u32(Vls + (j * 16 + t_r) * ALD + dnp * 16 + t_c);
                ldsm_x4_t(vl4[0], vl4[1], vl4[2], vl4[3], vb);
                #pragma unroll
                for (int hf = 0; hf < 2; hf++) {
                    const int dn = dnp * 2 + hf;
                    uint32_t bh2[2] = { vh4[hf*2], vh4[hf*2+1] };
                    uint32_t bl2[2] = { vl4[hf*2], vl4[hf*2+1] };
                    mma_f16(oacc[dn], ah, bh2);
                    mma_f16(oacc[dn], ah, bl2);
                }
            }
        }
    }

    // ---- epilogue: normalize, write fp16 O in [B*T, C] ----
    const int b = bh >> 4, h = bh & 15;
    #pragma unroll
    for (int r = 0; r < 2; r++) {
        const float inv = 1.0f / lsum[r];
        const int row = q0 + w * 16 + (lane >> 2) + r * 8;
        const size_t off = (size_t)(b * TT + row) * CC + h * DD;
        #pragma unroll
        for (int dn = 0; dn < 8; dn++) {
            const int col = dn * 8 + (lane & 3) * 2;
            *(uint32_t*)(g_Oh + off + col) =
                packf2(oacc[dn][2*r] * inv, oacc[dn][2*r+1] * inv);
        }
    }
}

// ---------------------------------------------------------------------------
extern "C" void kernel_launch(void* const* d_in, const int* in_sizes, int n_in,
                              void* d_out, int out_size)
{
    const float* x     = (const float*)d_in[0];
    const float* wqkv  = (const float*)d_in[1];
    const float* wproj = (const float*)d_in[2];
    float* out = (float*)d_out;

    cudaFuncSetAttribute((const void*)attn_mma_kernel,
                         cudaFuncAttributeMaxDynamicSharedMemorySize, ATTN_SMEM_BYTES);
    cudaFuncSetAttribute((const void*)mma_gemm_kernel<0>,
                         cudaFuncAttributeMaxDynamicSharedMemorySize, GEMM_SMEM_BYTES);
    cudaFuncSetAttribute((const void*)mma_gemm_kernel<1>,
                         cudaFuncAttributeMaxDynamicSharedMemorySize, GEMM_SMEM_BYTES);

    __half *xh, *wqh, *wql, *wph, *wpl, *oh;
    cudaGetSymbolAddress((void**)&xh,  g_Xh);
    cudaGetSymbolAddress((void**)&wqh, g_Wqh); cudaGetSymbolAddress((void**)&wql, g_Wql);
    cudaGetSymbolAddress((void**)&wph, g_Wph); cudaGetSymbolAddress((void**)&wpl, g_Wpl);
    cudaGetSymbolAddress((void**)&oh,  g_Oh);

    tohalf_kernel<<<(MM*CC/4 + 255)/256, 256>>>(x, xh, MM*CC/4);
    splith_kernel<<<(NQKV*CC/4 + 255)/256, 256>>>(wqkv, wqh, wql, NQKV*CC/4);
    splith_kernel<<<(CC*CC/4 + 255)/256, 256>>>(wproj, wph, wpl, CC*CC/4);

    mma_gemm_kernel<0><<<dim3(NQKV/128, MM/128), GEMM_THREADS, GEMM_SMEM_BYTES>>>(
        xh, wqh, wql, nullptr);

    attn_mma_kernel<<<dim3(TT/AQT, BB*HH), 256, ATTN_SMEM_BYTES>>>();

    mma_gemm_kernel<1><<<dim3(CC/128, MM/128), GEMM_THREADS, GEMM_SMEM_BYTES>>>(
        oh, wph, wpl, out);
}